// round 2
// baseline (speedup 1.0000x reference)
#include <cuda_runtime.h>
#include <math.h>

// FocalCTCLoss: B=256, T=1024, V=128, L=64, S=2L+1=129, blank=V-1.
// Scaled linear-domain CTC forward DP, one warp per batch element.
// Round 2: alpha recurrence, renorm, and epilogue in fp64 (discriminating
// experiment: structure vs fp32 numerics). p_hat pipeline stays fp32
// (bounded error <= ~2.4e-4 absolute in log-lik, provably negligible).

#define B_ 256
#define T_ 1024
#define V_ 128
#define L_ 64
#define EPS_ 1e-7f
#define PF 8      // gmem prefetch ring depth (float4 per lane per step)

__device__ float g_focal[B_];

__global__ void __launch_bounds__(64) ctc_kernel(const int* __restrict__ y_true,
                                                 const float* __restrict__ y_pred) {
    // two independent warps per block, one batch element each
    __shared__ float4 ytile4[2][2][32];   // [warp][parity][lane] staging of one vocab row
    const int warp = threadIdx.x >> 5;
    const int lane = threadIdx.x & 31;
    const int b = (blockIdx.x << 1) + warp;

    const float4* yrow = reinterpret_cast<const float4*>(y_pred) + (size_t)b * (T_ * V_ / 4);

    // Lane l owns states 4l..4l+3 (lane 31 additionally state 128).
    //   s=4l: blank   s=4l+1: label 2l   s=4l+2: blank   s=4l+3: label 2l+1
    const int* lr = y_true + b * L_;
    const int lab1 = lr[2 * lane];
    const int lab3 = lr[2 * lane + 1];
    const int labp = (lane > 0) ? lr[2 * lane - 1] : 0;
    const double sk1 = (lane > 0 && lab1 != labp) ? 1.0 : 0.0;  // skip into s=4l+1
    const double sk3 = (lab3 != lab1) ? 1.0 : 0.0;              // skip into s=4l+3
    const double m0 = (lane == 0) ? 0.0 : 1.0;

    // Prefetch ring: yv[t&7] holds the float4 (vocab [4l..4l+3]) for step t
    float4 yv[PF];
#pragma unroll
    for (int k = 0; k < PF; ++k) yv[k] = yrow[k * 32 + lane];

    float* const yt0 = reinterpret_cast<float*>(&ytile4[warp][0][0]);

    double a0 = 0., a1 = 0., a2 = 0., a3 = 0., a4 = 0.;
    double logAcc = 0.0;
    float pcB, pc1, pc3;     // p_hat (fp32) for the step about to be consumed

    // stage: compute p_hat for step t (ring slot k = t&7), refill ring slot.
    auto stage = [&](int t, int k, float& oB, float& o1, float& o3) {
        float4 y = yv[k];
        int tn = t + PF; if (tn > T_ - 1) tn = T_ - 1;   // clamped dummy refill (dead slots)
        yv[k] = yrow[tn * 32 + lane];
        float* yt = yt0 + (t & 1) * 128;                 // parity double-buffer
        *reinterpret_cast<float4*>(yt + lane * 4) = y;
        __syncwarp();
        float zp = (y.x + y.y) + (y.z + y.w);
        // fixed-point warp sum (exact to 2^-22 absolute/lane): one REDUX.SYNC.ADD
        int zi = __reduce_add_sync(0xffffffffu, __float2int_rn(zp * 4194304.0f));
        float Z = (float)zi * (1.0f / 4194304.0f) + (V_ * EPS_);
        float invZ = __fdividef(128.0f, Z);              // folds the 2^7 per-step scale
        float eZ = EPS_ * invZ;
        oB = fmaf(yt[127], invZ, eZ);                    // blank prob (v = 127)
        o1 = fmaf(yt[lab1], invZ, eZ);
        o3 = fmaf(yt[lab3], invZ, eZ);
    };

    // t = 0: stage and initialize alpha0[0] = p(0,blank), alpha0[1] = p(0,label0)
    stage(0, 0, pcB, pc1, pc3);
    if (lane == 0) { a0 = (double)pcB; a1 = (double)pc1; }

    for (int tb = 0; tb < T_; tb += PF) {
#pragma unroll
        for (int k = 0; k < PF; ++k) {
            const int t = tb + k;
            // stage step t+1 (long-latency gmem/smem/div) ahead of the DP of step t
            float pnB = pcB, pn1 = pc1, pn3 = pc3;
            if (t + 1 < T_) stage(t + 1, (k + 1) & (PF - 1), pnB, pn1, pn3);
            if (t > 0) {
                double pB = (double)pcB, p1 = (double)pc1, p3 = (double)pc3;
                double hi1 = __shfl_up_sync(0xffffffffu, a3, 1) * m0; // state 4l-1 (old)
                double n0 = (a0 + hi1) * pB;                          // s=4l   (blank)
                double n1 = fma(sk1, hi1, a1 + a0) * p1;              // s=4l+1
                double n2 = (a2 + a1) * pB;                           // s=4l+2 (blank)
                double n3 = fma(sk3, a1, a3 + a2) * p3;               // s=4l+3
                double n4 = (a4 + a3) * pB;                           // s=128 (lane 31)
                a0 = n0; a1 = n1; a2 = n2; a3 = n3;
                a4 = (lane == 31) ? n4 : 0.0;
            }
            if ((t & 63) == 63) {                 // exact renorm every 64 steps
                double s = ((a0 + a1) + (a2 + a3)) + a4;
#pragma unroll
                for (int off = 16; off; off >>= 1)
                    s += __shfl_xor_sync(0xffffffffu, s, off);
                double r = 1.0 / s;
                a0 *= r; a1 *= r; a2 *= r; a3 *= r; a4 *= r;
                logAcc += log(s);
            }
            pcB = pnB; pc1 = pn1; pc3 = pn3;
        }
    }

    if (lane == 31) {
        double lik = a3 + a4;                           // states 127 and 128
        // total applied scale: 128^1024  ->  1024*ln(128) = 7168*ln(2)
        double loglik = log(lik) + logAcc
                        - 7168.0 * 0.6931471805599453094172321214581766;
        double loss = -loglik;
        double p = exp(-loss);
        double om = 1.0 - p;
        g_focal[b] = (float)(0.25 * om * om * loss);    // ALPHA*(1-p)^GAMMA*loss
    }
}

__global__ void reduce_kernel(float* __restrict__ out) {
    __shared__ float sm[8];
    const int tid = threadIdx.x;
    float v = g_focal[tid];
#pragma unroll
    for (int off = 16; off; off >>= 1) v += __shfl_xor_sync(0xffffffffu, v, off);
    if ((tid & 31) == 0) sm[tid >> 5] = v;
    __syncthreads();
    if (tid < 8) {
        float w = sm[tid];
#pragma unroll
        for (int off = 4; off; off >>= 1) w += __shfl_xor_sync(0xffu, w, off);
        if (tid == 0) out[0] = w * (1.0f / (float)B_);
    }
}

extern "C" void kernel_launch(void* const* d_in, const int* in_sizes, int n_in,
                              void* d_out, int out_size) {
    const int* y_true;
    const float* y_pred;
    if (in_sizes[0] == B_ * L_) {
        y_true = (const int*)d_in[0];
        y_pred = (const float*)d_in[1];
    } else {
        y_true = (const int*)d_in[1];
        y_pred = (const float*)d_in[0];
    }
    ctc_kernel<<<B_ / 2, 64>>>(y_true, y_pred);
    reduce_kernel<<<1, 256>>>((float*)d_out);
}

// round 3
// speedup vs baseline: 3.2868x; 3.2868x over previous
#include <cuda_runtime.h>
#include <math.h>

// FocalCTCLoss: B=256, T=1024, V=128, L=64, S=129, blank=127.
// Log2-domain fp32 CTC DP (same numerics as the reference), split into a
// forward warp (alpha: t=0..511) and a backward warp (beta: t=1023..512)
// per batch element; combine via LSE_s(alpha_511[s] + beta_511[s]).
// 128 CTAs x 128 threads: warp w -> (element = 2*blk + (w&1), dir = w>>1),
// one warp per SMSP (MUFU-bound, no SMSP contention).

#define B_ 256
#define T_ 1024
#define V_ 128
#define L_ 64
#define EPS_ 1e-7f
#define PF 8
#define NEG (-1e30f)
#define LN2_ 0.6931471805599453f

__device__ float g_focal[B_];

__device__ __forceinline__ float ex2(float x) { float r; asm("ex2.approx.ftz.f32 %0,%1;" : "=f"(r) : "f"(x)); return r; }
__device__ __forceinline__ float lg2(float x) { float r; asm("lg2.approx.ftz.f32 %0,%1;" : "=f"(r) : "f"(x)); return r; }

__device__ __forceinline__ float lse2(float x, float y) {
    float m = fmaxf(x, y);
    return m + lg2(ex2(x - m) + ex2(y - m));
}
__device__ __forceinline__ float lse3(float x, float y, float z) {
    float m = fmaxf(fmaxf(x, y), z);
    return m + lg2(ex2(x - m) + ex2(y - m) + ex2(z - m));
}

__global__ void __launch_bounds__(128) ctc_kernel(const int* __restrict__ y_true,
                                                  const float* __restrict__ y_pred) {
    __shared__ float ytile[4][2][128];     // per-warp vocab-row staging (parity buffered)
    __shared__ float sbeta[2][132];        // beta_511 handoff, per element

    const int lane = threadIdx.x & 31;
    const int wid = threadIdx.x >> 5;
    const bool fwd = (wid < 2);
    const int e = wid & 1;
    const int b = (blockIdx.x << 1) + e;

    const float4* yrow = reinterpret_cast<const float4*>(y_pred) + (size_t)b * (T_ * V_ / 4);

    // Lane l owns states 4l..4l+3 (lane 31 also s=128).
    //  s=4l: blank  s=4l+1: label 2l  s=4l+2: blank  s=4l+3: label 2l+1
    const int* lr = y_true + b * L_;
    const int lab1 = lr[2 * lane];
    const int lab3 = lr[2 * lane + 1];
    const int labp = (lane > 0) ? lr[2 * lane - 1] : 0;
    const float hsk1 = (lane > 0 && lab1 != labp) ? 0.0f : NEG; // skip into s=4l+1
    const float hsk3 = (lab3 != lab1) ? 0.0f : NEG;             // skip into s=4l+3

    // Prefetch ring: slot i&7 holds data for iteration i (fwd t=i, bwd t=1023-i)
    float4 yv[PF];
#pragma unroll
    for (int k = 0; k < PF; ++k) {
        int t = fwd ? k : (1023 - k);
        yv[k] = yrow[t * 32 + lane];
    }
    float* const ytBase = &ytile[wid][0][0];

    // p-values (log2 of normalized probs) for blank / lab1 / lab3
    float ppB, pp1, pp3;   // stage(i-2)
    float pcB, pc1, pc3;   // stage(i-1)
    float pnB, pn1, pn3;   // stage(i)

    auto stage = [&](int i, float& oB, float& o1, float& o3) {
        const int slot = i & 7;
        float4 y = yv[slot];
        int tref = fwd ? (i + PF) : (1023 - i - PF);      // always in-bounds (i<=511)
        yv[slot] = yrow[tref * 32 + lane];
        float* yt = ytBase + (i & 1) * 128;
        *reinterpret_cast<float4*>(yt + lane * 4) = y;
        __syncwarp();
        float zp = (y.x + y.y) + (y.z + y.w);
        int zi = __reduce_add_sync(0xffffffffu, __float2int_rn(zp * 4194304.0f));
        float Z = (float)zi * (1.0f / 4194304.0f) + (V_ * EPS_);
        float lZ = lg2(Z);
        oB = lg2(yt[127] + EPS_) - lZ;
        o1 = lg2(yt[lab1] + EPS_) - lZ;
        o3 = lg2(yt[lab3] + EPS_) - lZ;
    };

    float a0 = NEG, a1 = NEG, a2 = NEG, a3 = NEG, a4 = NEG;

    stage(0, pcB, pc1, pc3);
    if (fwd) {                                   // alpha_0 init
        if (lane == 0) { a0 = pcB; a1 = pc1; }
    } else {                                     // beta_1023 init: states 127,128 = 0
        if (lane == 31) { a3 = 0.0f; a4 = 0.0f; }
    }

    // peel i=1
    stage(1, pnB, pn1, pn3);
    ppB = pcB; pp1 = pc1; pp3 = pc3;
    pcB = pnB; pc1 = pn1; pc3 = pn3;

#pragma unroll 8
    for (int i = 2; i < 514; ++i) {              // 512 iterations, DP step j = i-1
        if (i <= 511) stage(i, pnB, pn1, pn3);   // long-latency work, consumed next iter
        if (fwd) {
            if (i <= 512) {                      // alpha_j, j=1..511, uses stage(j)=pc
                float hi1 = __shfl_up_sync(0xffffffffu, a3, 1);
                hi1 = (lane == 0) ? NEG : hi1;
                float n0 = lse2(a0, hi1) + pcB;
                float n1 = lse3(a1, a0, hi1 + hsk1) + pc1;
                float n2 = lse2(a2, a1) + pcB;
                float n3 = lse3(a3, a2, a1 + hsk3) + pc3;
                float n4 = lse2(a4, a3) + pcB;   // s=128 (real only on lane 31)
                a0 = n0; a1 = n1; a2 = n2; a3 = n3; a4 = n4;
            }
        } else {                                 // beta_{1023-j}, uses stage(j-1)=pp
            float c1 = a1 + pp1;                 // b[s+? ] + p_{t+1}[ext]
            float c3 = a3 + pp3;
            float cB2 = a2 + ppB;
            float w = c1 + hsk1;                 // next-lane skip candidate (has own lp,sk)
            float wd = __shfl_down_sync(0xffffffffu, w, 1);
            float b0d = __shfl_down_sync(0xffffffffu, a0, 1);
            float t1 = (lane == 31) ? a4 : b0d;  // beta[s+1] for state 4l+3
            float t2 = (lane == 31) ? NEG : wd;  // beta[s+2] (+lp+skip) for 4l+3
            float n0 = lse2(a0 + ppB, c1);
            float n1 = lse3(c1, cB2, c3 + hsk3);
            float n2 = lse2(cB2, c3);
            float n3 = lse3(c3, t1 + ppB, t2);
            float n4 = a4 + ppB;                 // s=128: only self-loop
            a0 = n0; a1 = n1; a2 = n2; a3 = n3; a4 = n4;
        }
        ppB = pcB; pp1 = pc1; pp3 = pc3;
        pcB = pnB; pc1 = pn1; pc3 = pn3;
    }

    // combine: loglik = LSE_s(alpha_511[s] + beta_511[s])
    if (!fwd) {
        sbeta[e][4 * lane + 0] = a0;
        sbeta[e][4 * lane + 1] = a1;
        sbeta[e][4 * lane + 2] = a2;
        sbeta[e][4 * lane + 3] = a3;
        if (lane == 31) sbeta[e][128] = a4;
    }
    __syncthreads();
    if (fwd) {
        float c0 = a0 + sbeta[e][4 * lane + 0];
        float c1 = a1 + sbeta[e][4 * lane + 1];
        float c2 = a2 + sbeta[e][4 * lane + 2];
        float c3 = a3 + sbeta[e][4 * lane + 3];
        float c4 = (lane == 31) ? (a4 + sbeta[e][128]) : NEG;
        float m = fmaxf(fmaxf(fmaxf(c0, c1), fmaxf(c2, c3)), c4);
#pragma unroll
        for (int off = 16; off; off >>= 1)
            m = fmaxf(m, __shfl_xor_sync(0xffffffffu, m, off));
        float s = ex2(c0 - m) + ex2(c1 - m) + ex2(c2 - m) + ex2(c3 - m) + ex2(c4 - m);
#pragma unroll
        for (int off = 16; off; off >>= 1)
            s += __shfl_xor_sync(0xffffffffu, s, off);
        if (lane == 0) {
            float loglik = (m + lg2(s)) * LN2_;  // log2 units -> nats
            float loss = -loglik;
            float p = expf(-loss);
            float om = 1.0f - p;
            g_focal[b] = 0.25f * om * om * loss;
        }
    }
}

__global__ void reduce_kernel(float* __restrict__ out) {
    __shared__ float sm[8];
    const int tid = threadIdx.x;
    float v = g_focal[tid];
#pragma unroll
    for (int off = 16; off; off >>= 1) v += __shfl_xor_sync(0xffffffffu, v, off);
    if ((tid & 31) == 0) sm[tid >> 5] = v;
    __syncthreads();
    if (tid < 8) {
        float w = sm[tid];
#pragma unroll
        for (int off = 4; off; off >>= 1) w += __shfl_xor_sync(0xffu, w, off);
        if (tid == 0) out[0] = w * (1.0f / (float)B_);
    }
}

extern "C" void kernel_launch(void* const* d_in, const int* in_sizes, int n_in,
                              void* d_out, int out_size) {
    const int* y_true;
    const float* y_pred;
    if (in_sizes[0] == B_ * L_) {
        y_true = (const int*)d_in[0];
        y_pred = (const float*)d_in[1];
    } else {
        y_true = (const int*)d_in[1];
        y_pred = (const float*)d_in[0];
    }
    ctc_kernel<<<B_ / 2, 128>>>(y_true, y_pred);
    reduce_kernel<<<1, 256>>>((float*)d_out);
}

// round 4
// speedup vs baseline: 3.8994x; 1.1864x over previous
#include <cuda_runtime.h>
#include <math.h>

// FocalCTCLoss: B=256, T=1024, V=128, L=64, S=129, blank=127.
// Log2-domain fp32 CTC DP; forward warp (alpha t=0..511) and backward warp
// (beta t=1023..512) per element; combine via LSE_s(alpha_511 + beta_511).
// Grid 64 x 256: warp w -> element e = w>>1 (b = 4*blk+e), dir = w&1.
// 2 warps per SMSP for latency hiding; fwd/bwd are separate straight-line
// loops (no interior branches); stage() runs 2 iterations ahead.

#define B_ 256
#define T_ 1024
#define V_ 128
#define L_ 64
#define EPS_ 1e-7f
#define PF 8
#define NEG (-1e30f)
#define LN2_ 0.6931471805599453f

__device__ float g_focal[B_];

__device__ __forceinline__ float ex2(float x) { float r; asm("ex2.approx.ftz.f32 %0,%1;" : "=f"(r) : "f"(x)); return r; }
__device__ __forceinline__ float lg2(float x) { float r; asm("lg2.approx.ftz.f32 %0,%1;" : "=f"(r) : "f"(x)); return r; }

__device__ __forceinline__ float lse2(float x, float y) {
    float m = fmaxf(x, y);
    return m + lg2(ex2(x - m) + ex2(y - m));
}
__device__ __forceinline__ float lse3(float x, float y, float z) {
    float m = fmaxf(fmaxf(x, y), z);
    return m + lg2(ex2(x - m) + ex2(y - m) + ex2(z - m));
}

__global__ void __launch_bounds__(256) ctc_kernel(const int* __restrict__ y_true,
                                                  const float* __restrict__ y_pred) {
    __shared__ float ytile[8][2][128];   // per-warp vocab-row staging (parity buffered)
    __shared__ float sbeta[4][132];      // beta_511 handoff per element

    const int lane = threadIdx.x & 31;
    const int wid = threadIdx.x >> 5;
    const bool fwd = ((wid & 1) == 0);
    const int e = wid >> 1;
    const int b = (blockIdx.x << 2) + e;

    const float4* yrow = reinterpret_cast<const float4*>(y_pred) + (size_t)b * (T_ * V_ / 4);

    // Lane l owns states 4l..4l+3 (lane 31 also s=128).
    //  s=4l: blank  s=4l+1: label 2l  s=4l+2: blank  s=4l+3: label 2l+1
    const int* lr = y_true + b * L_;
    const int lab1 = lr[2 * lane];
    const int lab3 = lr[2 * lane + 1];
    const int labp = (lane > 0) ? lr[2 * lane - 1] : 0;
    const float hsk1 = (lane > 0 && lab1 != labp) ? 0.0f : NEG;  // skip into s=4l+1
    const float hsk3 = (lab3 != lab1) ? 0.0f : NEG;              // skip into s=4l+3

    // Prefetch ring: slot i&7 holds data for stage(i): fwd t=i, bwd t=1023-i
    float4 yv[PF];
#pragma unroll
    for (int k = 0; k < PF; ++k) {
        int t = fwd ? k : (1023 - k);
        yv[k] = yrow[t * 32 + lane];
    }
    float* const ytBase = &ytile[wid][0][0];

    float ppB, pp1, pp3;   // stage(i-2): consumed by DP at iteration i
    float pcB, pc1, pc3;   // stage(i-1)
    float pnB, pn1, pn3;   // stage(i)

    // stage(i): log2-normalized probs for this warp's timestep i; refill ring.
    auto stage = [&](int i, float& oB, float& o1, float& o3) {
        const int slot = i & 7;
        float4 y = yv[slot];
        int tref = fwd ? (i + PF) : (1023 - i - PF);   // in-bounds for i <= 511
        yv[slot] = yrow[tref * 32 + lane];
        float* yt = ytBase + (i & 1) * 128;
        *reinterpret_cast<float4*>(yt + lane * 4) = y;
        __syncwarp();
        float zp = (y.x + y.y) + (y.z + y.w);
        int zi = __reduce_add_sync(0xffffffffu, __float2int_rn(zp * 4194304.0f));
        float Z = (float)zi * (1.0f / 4194304.0f) + (V_ * EPS_);
        float lZ = lg2(Z);
        oB = lg2(yt[127] + EPS_) - lZ;
        o1 = lg2(yt[lab1] + EPS_) - lZ;
        o3 = lg2(yt[lab3] + EPS_) - lZ;
    };

    float a0 = NEG, a1 = NEG, a2 = NEG, a3 = NEG, a4 = NEG;

    if (fwd) {
        // ---------------- forward: alpha_0 .. alpha_511 ----------------
        stage(0, ppB, pp1, pp3);
        if (lane == 0) { a0 = ppB; a1 = pp1; }          // alpha_0 init
        stage(1, ppB, pp1, pp3);
        stage(2, pcB, pc1, pc3);

#define FWD_DP()                                                          \
        {                                                                 \
            float hi1 = __shfl_up_sync(0xffffffffu, a3, 1);               \
            hi1 = (lane == 0) ? NEG : hi1;                                \
            float n0 = lse2(a0, hi1) + ppB;                               \
            float n1 = lse3(a1, a0, hi1 + hsk1) + pp1;                    \
            float n2 = lse2(a2, a1) + ppB;                                \
            float n3 = lse3(a3, a2, a1 + hsk3) + pp3;                     \
            float n4 = lse2(a4, a3) + ppB;                                \
            a0 = n0; a1 = n1; a2 = n2; a3 = n3; a4 = n4;                  \
        }

#pragma unroll 4
        for (int i = 3; i <= 511; ++i) {   // DP step i-2 (alpha_1..alpha_509)
            stage(i, pnB, pn1, pn3);
            FWD_DP();
            ppB = pcB; pp1 = pc1; pp3 = pc3;
            pcB = pnB; pc1 = pn1; pc3 = pn3;
        }
        FWD_DP();                          // alpha_510 (uses stage(510))
        ppB = pcB; pp1 = pc1; pp3 = pc3;
        FWD_DP();                          // alpha_511 (uses stage(511))
    } else {
        // ---------------- backward: beta_1022 .. beta_511 ----------------
        stage(0, ppB, pp1, pp3);           // lp_1023
        if (lane == 31) { a3 = 0.0f; a4 = 0.0f; }       // beta_1023 init
        stage(1, pcB, pc1, pc3);

#define BWD_DP()                                                          \
        {                                                                 \
            float c1 = a1 + pp1;                                          \
            float c3 = a3 + pp3;                                          \
            float cB2 = a2 + ppB;                                         \
            float w = c1 + hsk1;                                          \
            float wd = __shfl_down_sync(0xffffffffu, w, 1);               \
            float b0d = __shfl_down_sync(0xffffffffu, a0, 1);             \
            float t1 = (lane == 31) ? a4 : b0d;                           \
            float t2 = (lane == 31) ? NEG : wd;                           \
            float n0 = lse2(a0 + ppB, c1);                                \
            float n1 = lse3(c1, cB2, c3 + hsk3);                          \
            float n2 = lse2(cB2, c3);                                     \
            float n3 = lse3(c3, t1 + ppB, t2);                            \
            float n4 = a4 + ppB;                                          \
            a0 = n0; a1 = n1; a2 = n2; a3 = n3; a4 = n4;                  \
        }

#pragma unroll 4
        for (int i = 2; i <= 511; ++i) {   // beta_{1024-i} (beta_1022..beta_513)
            stage(i, pnB, pn1, pn3);
            BWD_DP();
            ppB = pcB; pp1 = pc1; pp3 = pc3;
            pcB = pnB; pc1 = pn1; pc3 = pn3;
        }
        BWD_DP();                          // beta_512 (uses stage(510))
        ppB = pcB; pp1 = pc1; pp3 = pc3;
        BWD_DP();                          // beta_511 (uses stage(511))

        sbeta[e][4 * lane + 0] = a0;
        sbeta[e][4 * lane + 1] = a1;
        sbeta[e][4 * lane + 2] = a2;
        sbeta[e][4 * lane + 3] = a3;
        if (lane == 31) sbeta[e][128] = a4;
    }
    __syncthreads();

    if (fwd) {
        // loglik = LSE_s(alpha_511[s] + beta_511[s])
        float c0 = a0 + sbeta[e][4 * lane + 0];
        float c1 = a1 + sbeta[e][4 * lane + 1];
        float c2 = a2 + sbeta[e][4 * lane + 2];
        float c3 = a3 + sbeta[e][4 * lane + 3];
        float c4 = (lane == 31) ? (a4 + sbeta[e][128]) : NEG;
        float m = fmaxf(fmaxf(fmaxf(c0, c1), fmaxf(c2, c3)), c4);
#pragma unroll
        for (int off = 16; off; off >>= 1)
            m = fmaxf(m, __shfl_xor_sync(0xffffffffu, m, off));
        float s = ex2(c0 - m) + ex2(c1 - m) + ex2(c2 - m) + ex2(c3 - m) + ex2(c4 - m);
#pragma unroll
        for (int off = 16; off; off >>= 1)
            s += __shfl_xor_sync(0xffffffffu, s, off);
        if (lane == 0) {
            float loglik = (m + lg2(s)) * LN2_;    // log2 units -> nats
            float loss = -loglik;
            float p = expf(-loss);
            float om = 1.0f - p;
            g_focal[b] = 0.25f * om * om * loss;
        }
    }
}

__global__ void reduce_kernel(float* __restrict__ out) {
    __shared__ float sm[8];
    const int tid = threadIdx.x;
    float v = g_focal[tid];
#pragma unroll
    for (int off = 16; off; off >>= 1) v += __shfl_xor_sync(0xffffffffu, v, off);
    if ((tid & 31) == 0) sm[tid >> 5] = v;
    __syncthreads();
    if (tid < 8) {
        float w = sm[tid];
#pragma unroll
        for (int off = 4; off; off >>= 1) w += __shfl_xor_sync(0xffu, w, off);
        if (tid == 0) out[0] = w * (1.0f / (float)B_);
    }
}

// ncu alignment pads: with 5 launches per call, capture (-s 5 -c 1) lands on
// ctc_kernel instead of reduce_kernel. ~1 us each; diagnostic cost.
__global__ void pad_kernel() {}

extern "C" void kernel_launch(void* const* d_in, const int* in_sizes, int n_in,
                              void* d_out, int out_size) {
    const int* y_true;
    const float* y_pred;
    if (in_sizes[0] == B_ * L_) {
        y_true = (const int*)d_in[0];
        y_pred = (const float*)d_in[1];
    } else {
        y_true = (const int*)d_in[1];
        y_pred = (const float*)d_in[0];
    }
    ctc_kernel<<<B_ / 4, 256>>>(y_true, y_pred);
    reduce_kernel<<<1, 256>>>((float*)d_out);
    pad_kernel<<<1, 32>>>();
    pad_kernel<<<1, 32>>>();
    pad_kernel<<<1, 32>>>();
}

// round 5
// speedup vs baseline: 4.0779x; 1.0458x over previous
#include <cuda_runtime.h>
#include <math.h>

// FocalCTCLoss: B=256, T=1024, V=128, L=64, S=129, blank=127.
// Log2-domain fp32 CTC DP; forward warp (alpha t=0..511) and backward warp
// (beta t=1023..512) per element; combine via LSE_s(alpha_511 + beta_511).
// SINGLE fused kernel: grid 128 x 128 (4 warps/CTA = 2 elements/CTA,
// 1 warp per SMSP on 128 SMs, single wave). Final mean via last-CTA
// deterministic reduction (threadfence + atomic ticket).

#define B_ 256
#define T_ 1024
#define V_ 128
#define L_ 64
#define EPS_ 1e-7f
#define PF 8
#define NEG (-1e30f)
#define LN2_ 0.6931471805599453f

__device__ float g_focal[B_];
__device__ unsigned int g_count;   // zero-initialized at module load; reset by last CTA

__device__ __forceinline__ float ex2(float x) { float r; asm("ex2.approx.ftz.f32 %0,%1;" : "=f"(r) : "f"(x)); return r; }
__device__ __forceinline__ float lg2(float x) { float r; asm("lg2.approx.ftz.f32 %0,%1;" : "=f"(r) : "f"(x)); return r; }

__device__ __forceinline__ float lse2(float x, float y) {
    float m = fmaxf(x, y);
    return m + lg2(ex2(x - m) + ex2(y - m));
}
__device__ __forceinline__ float lse3(float x, float y, float z) {
    float m = fmaxf(fmaxf(x, y), z);
    return m + lg2(ex2(x - m) + ex2(y - m) + ex2(z - m));
}

__global__ void __launch_bounds__(128) ctc_kernel(const int* __restrict__ y_true,
                                                  const float* __restrict__ y_pred,
                                                  float* __restrict__ out) {
    __shared__ float ytile[4][2][128];   // per-warp vocab-row staging (parity buffered)
    __shared__ float sbeta[2][132];      // beta_511 handoff per element
    __shared__ float sfocal[2];
    __shared__ unsigned int sIsLast;

    const int lane = threadIdx.x & 31;
    const int wid = threadIdx.x >> 5;
    const bool fwd = ((wid & 1) == 0);
    const int e = wid >> 1;
    const int b = (blockIdx.x << 1) + e;

    const float4* yrow = reinterpret_cast<const float4*>(y_pred) + (size_t)b * (T_ * V_ / 4);

    // Lane l owns states 4l..4l+3 (lane 31 also s=128).
    //  s=4l: blank  s=4l+1: label 2l  s=4l+2: blank  s=4l+3: label 2l+1
    const int* lr = y_true + b * L_;
    const int lab1 = lr[2 * lane];
    const int lab3 = lr[2 * lane + 1];
    const int labp = (lane > 0) ? lr[2 * lane - 1] : 0;
    const float hsk1 = (lane > 0 && lab1 != labp) ? 0.0f : NEG;  // skip into s=4l+1
    const float hsk3 = (lab3 != lab1) ? 0.0f : NEG;              // skip into s=4l+3

    // Prefetch ring: slot i&7 holds data for stage(i): fwd t=i, bwd t=1023-i
    float4 yv[PF];
#pragma unroll
    for (int k = 0; k < PF; ++k) {
        int t = fwd ? k : (1023 - k);
        yv[k] = yrow[t * 32 + lane];
    }
    float* const ytBase = &ytile[wid][0][0];

    float ppB, pp1, pp3;   // stage(i-2): consumed by DP at iteration i
    float pcB, pc1, pc3;   // stage(i-1)
    float pnB, pn1, pn3;   // stage(i)

    // stage(i): log2-normalized probs for this warp's timestep i; refill ring.
    auto stage = [&](int i, float& oB, float& o1, float& o3) {
        const int slot = i & 7;
        float4 y = yv[slot];
        int tref = fwd ? (i + PF) : (1023 - i - PF);   // in-bounds for i <= 511
        yv[slot] = yrow[tref * 32 + lane];
        float* yt = ytBase + (i & 1) * 128;
        *reinterpret_cast<float4*>(yt + lane * 4) = y;
        __syncwarp();
        float zp = (y.x + y.y) + (y.z + y.w);
        int zi = __reduce_add_sync(0xffffffffu, __float2int_rn(zp * 4194304.0f));
        float Z = (float)zi * (1.0f / 4194304.0f) + (V_ * EPS_);
        float lZ = lg2(Z);
        oB = lg2(yt[127] + EPS_) - lZ;
        o1 = lg2(yt[lab1] + EPS_) - lZ;
        o3 = lg2(yt[lab3] + EPS_) - lZ;
    };

    float a0 = NEG, a1 = NEG, a2 = NEG, a3 = NEG, a4 = NEG;

    if (fwd) {
        // ---------------- forward: alpha_0 .. alpha_511 ----------------
        stage(0, ppB, pp1, pp3);
        if (lane == 0) { a0 = ppB; a1 = pp1; }          // alpha_0 init
        stage(1, ppB, pp1, pp3);
        stage(2, pcB, pc1, pc3);

#define FWD_DP()                                                          \
        {                                                                 \
            float hi1 = __shfl_up_sync(0xffffffffu, a3, 1);               \
            hi1 = (lane == 0) ? NEG : hi1;                                \
            float n0 = lse2(a0, hi1) + ppB;                               \
            float n1 = lse3(a1, a0, hi1 + hsk1) + pp1;                    \
            float n2 = lse2(a2, a1) + ppB;                                \
            float n3 = lse3(a3, a2, a1 + hsk3) + pp3;                     \
            float n4 = lse2(a4, a3) + ppB;                                \
            a0 = n0; a1 = n1; a2 = n2; a3 = n3; a4 = n4;                  \
        }

#pragma unroll 4
        for (int i = 3; i <= 511; ++i) {   // DP step i-2 (alpha_1..alpha_509)
            stage(i, pnB, pn1, pn3);
            FWD_DP();
            ppB = pcB; pp1 = pc1; pp3 = pc3;
            pcB = pnB; pc1 = pn1; pc3 = pn3;
        }
        FWD_DP();                          // alpha_510 (uses stage(510))
        ppB = pcB; pp1 = pc1; pp3 = pc3;
        FWD_DP();                          // alpha_511 (uses stage(511))
    } else {
        // ---------------- backward: beta_1022 .. beta_511 ----------------
        stage(0, ppB, pp1, pp3);           // lp_1023
        if (lane == 31) { a3 = 0.0f; a4 = 0.0f; }       // beta_1023 init
        stage(1, pcB, pc1, pc3);

#define BWD_DP()                                                          \
        {                                                                 \
            float c1 = a1 + pp1;                                          \
            float c3 = a3 + pp3;                                          \
            float cB2 = a2 + ppB;                                         \
            float w = c1 + hsk1;                                          \
            float wd = __shfl_down_sync(0xffffffffu, w, 1);               \
            float b0d = __shfl_down_sync(0xffffffffu, a0, 1);             \
            float t1 = (lane == 31) ? a4 : b0d;                           \
            float t2 = (lane == 31) ? NEG : wd;                           \
            float n0 = lse2(a0 + ppB, c1);                                \
            float n1 = lse3(c1, cB2, c3 + hsk3);                          \
            float n2 = lse2(cB2, c3);                                     \
            float n3 = lse3(c3, t1 + ppB, t2);                            \
            float n4 = a4 + ppB;                                          \
            a0 = n0; a1 = n1; a2 = n2; a3 = n3; a4 = n4;                  \
        }

#pragma unroll 4
        for (int i = 2; i <= 511; ++i) {   // beta_{1024-i} (beta_1022..beta_513)
            stage(i, pnB, pn1, pn3);
            BWD_DP();
            ppB = pcB; pp1 = pc1; pp3 = pc3;
            pcB = pnB; pc1 = pn1; pc3 = pn3;
        }
        BWD_DP();                          // beta_512 (uses stage(510))
        ppB = pcB; pp1 = pc1; pp3 = pc3;
        BWD_DP();                          // beta_511 (uses stage(511))

        sbeta[e][4 * lane + 0] = a0;
        sbeta[e][4 * lane + 1] = a1;
        sbeta[e][4 * lane + 2] = a2;
        sbeta[e][4 * lane + 3] = a3;
        if (lane == 31) sbeta[e][128] = a4;
    }
    __syncthreads();

    if (fwd) {
        // loglik = LSE_s(alpha_511[s] + beta_511[s])
        float c0 = a0 + sbeta[e][4 * lane + 0];
        float c1 = a1 + sbeta[e][4 * lane + 1];
        float c2 = a2 + sbeta[e][4 * lane + 2];
        float c3 = a3 + sbeta[e][4 * lane + 3];
        float c4 = (lane == 31) ? (a4 + sbeta[e][128]) : NEG;
        float m = fmaxf(fmaxf(fmaxf(c0, c1), fmaxf(c2, c3)), c4);
#pragma unroll
        for (int off = 16; off; off >>= 1)
            m = fmaxf(m, __shfl_xor_sync(0xffffffffu, m, off));
        float s = ex2(c0 - m) + ex2(c1 - m) + ex2(c2 - m) + ex2(c3 - m) + ex2(c4 - m);
#pragma unroll
        for (int off = 16; off; off >>= 1)
            s += __shfl_xor_sync(0xffffffffu, s, off);
        if (lane == 0) {
            float loglik = (m + lg2(s)) * LN2_;    // log2 units -> nats
            float loss = -loglik;
            float p = expf(-loss);
            float om = 1.0f - p;
            sfocal[e] = 0.25f * om * om * loss;
        }
    }
    __syncthreads();

    // ---- fused mean: last CTA reduces all 256 focal values deterministically ----
    if (threadIdx.x == 0) {
        g_focal[b] = sfocal[0];          // b == 2*blk (e==0 for thread 0)
        g_focal[b + 1] = sfocal[1];
        __threadfence();
        unsigned int old = atomicAdd(&g_count, 1u);
        sIsLast = (old == gridDim.x - 1) ? 1u : 0u;
    }
    __syncthreads();
    if (sIsLast) {
        float v = g_focal[threadIdx.x] + g_focal[threadIdx.x + 128];
#pragma unroll
        for (int off = 16; off; off >>= 1)
            v += __shfl_xor_sync(0xffffffffu, v, off);
        __shared__ float sm[4];
        if (lane == 0) sm[wid] = v;
        __syncthreads();
        if (threadIdx.x == 0) {
            out[0] = (sm[0] + sm[1] + sm[2] + sm[3]) * (1.0f / (float)B_);
            g_count = 0;                 // reset for next (graph-replayed) call
        }
    }
}

extern "C" void kernel_launch(void* const* d_in, const int* in_sizes, int n_in,
                              void* d_out, int out_size) {
    const int* y_true;
    const float* y_pred;
    if (in_sizes[0] == B_ * L_) {
        y_true = (const int*)d_in[0];
        y_pred = (const float*)d_in[1];
    } else {
        y_true = (const int*)d_in[1];
        y_pred = (const float*)d_in[0];
    }
    ctc_kernel<<<B_ / 2, 128>>>(y_true, y_pred, (float*)d_out);
}

// round 6
// speedup vs baseline: 4.8737x; 1.1951x over previous
#include <cuda_runtime.h>
#include <math.h>

// FocalCTCLoss: B=256, T=1024, V=128, L=64, S=129, blank=127.
// Log2-domain fp32 CTC DP on UNNORMALIZED lq=lg2(y+eps); the softmax
// normalizer Sum_t lg2(Z_t) is a uniform per-step shift, accumulated as a
// scalar (zAcc) off the DP critical path and subtracted once at the end.
// Forward warp (t=0..511) + backward warp (t=1023..512) per element;
// combine via LSE_s(alpha'_511 + beta'_511) - zfwd - zbwd.
// No smem/syncwarp/LDS in the hot loop: label values come from scattered
// prefetched LDG (L1 hits behind the float4 Z-loads); blank via SHFL lane31.
// Grid 128 x 128: 1 warp/SMSP on 128 SMs, single wave. Fused last-CTA mean.

#define B_ 256
#define T_ 1024
#define V_ 128
#define L_ 64
#define EPS_ 1e-7f
#define NEG (-1e30f)
#define LN2_ 0.6931471805599453f

__device__ float g_focal[B_];
__device__ unsigned int g_count;   // zero-init at load; reset by last CTA

__device__ __forceinline__ float ex2(float x) { float r; asm("ex2.approx.ftz.f32 %0,%1;" : "=f"(r) : "f"(x)); return r; }
__device__ __forceinline__ float lg2(float x) { float r; asm("lg2.approx.ftz.f32 %0,%1;" : "=f"(r) : "f"(x)); return r; }

// 2-MUFU LSE2: max + lg2(1 + ex2(min-max))
__device__ __forceinline__ float lse2(float x, float y) {
    float m = fmaxf(x, y), lo = fminf(x, y);
    return m + lg2(1.0f + ex2(lo - m));
}
// 3-MUFU LSE3: the max term contributes ex2(0)=1 exactly
__device__ __forceinline__ float lse3(float x, float y, float z) {
    float mx = fmaxf(x, y), mn = fminf(x, y);
    float m = fmaxf(mx, z);
    float mid = fmaxf(fminf(mx, z), mn);
    float lo = fminf(mn, z);
    return m + lg2(1.0f + ex2(mid - m) + ex2(lo - m));
}

__global__ void __launch_bounds__(128) ctc_kernel(const int* __restrict__ y_true,
                                                  const float* __restrict__ y_pred,
                                                  float* __restrict__ out) {
    __shared__ float sbeta[2][132];      // beta'_511 (129 states) + zbwd at [129]
    __shared__ float sfocal[2];
    __shared__ unsigned int sIsLast;

    const int lane = threadIdx.x & 31;
    const int wid = threadIdx.x >> 5;
    const bool fwd = ((wid & 1) == 0);
    const int e = wid >> 1;
    const int b = (blockIdx.x << 1) + e;

    const float* yb = y_pred + (size_t)b * (T_ * V_);
    const float4* yrow4 = reinterpret_cast<const float4*>(yb);

    // Lane l owns states 4l..4l+3 (lane 31 also s=128).
    //  s=4l: blank  s=4l+1: label 2l  s=4l+2: blank  s=4l+3: label 2l+1
    const int* lr = y_true + b * L_;
    const int lab1 = lr[2 * lane];
    const int lab3 = lr[2 * lane + 1];
    const int labp = (lane > 0) ? lr[2 * lane - 1] : 0;
    const float hsk1 = (lane > 0 && lab1 != labp) ? 0.0f : NEG;  // skip into s=4l+1
    const float hsk3 = (lab3 != lab1) ? 0.0f : NEG;              // skip into s=4l+3

    // iteration i -> timestep t(i) = t0 + dir*i
    const int dir = fwd ? 1 : -1;
    const int t0 = fwd ? 0 : 1023;

    // Prefetch rings: rv (float4 rows, depth 8, feeds Z + blank),
    //                 g1/g3 (scattered label gathers, depth 4, L1 hits)
    float4 rv[8];
    float g1[4], g3[4];
#pragma unroll
    for (int k = 0; k < 8; ++k) rv[k] = yrow4[(t0 + dir * k) * 32 + lane];
#pragma unroll
    for (int k = 0; k < 4; ++k) {
        const float* r = yb + (t0 + dir * k) * V_;
        g1[k] = r[lab1]; g3[k] = r[lab3];
    }

    float zAcc = 0.0f;
    float a0 = NEG, a1 = NEG, a2 = NEG, a3 = NEG, a4 = NEG;

    // consume(i): unnormalized lq's for step i; Z accumulation; ring refills.
    auto consume = [&](int i, float& oB, float& o1, float& o3) {
        const int s8 = i & 7, s4 = i & 3;
        float4 y = rv[s8];
        float y1 = g1[s4], y3 = g3[s4];
        rv[s8] = yrow4[(t0 + dir * (i + 8)) * 32 + lane];      // t in [0,1023] always
        const float* r = yb + (t0 + dir * (i + 4)) * V_;
        g1[s4] = r[lab1]; g3[s4] = r[lab3];
        float zp = (y.x + y.y) + (y.z + y.w);
        int zi = __reduce_add_sync(0xffffffffu, __float2int_rn(zp * 4194304.0f));
        float Z = (float)zi * (1.0f / 4194304.0f) + (V_ * EPS_);
        zAcc += lg2(Z);                                        // off DP path
        float yB = __shfl_sync(0xffffffffu, y.w, 31);          // y[t][127]
        oB = lg2(yB + EPS_);
        o1 = lg2(y1 + EPS_);
        o3 = lg2(y3 + EPS_);
    };

    float pB, p1, p3;

    if (fwd) {
        // -------- forward: alpha'_0 .. alpha'_511 --------
        consume(0, pB, p1, p3);
        if (lane == 0) { a0 = pB; a1 = p1; }                   // alpha'_0 init
#pragma unroll 4
        for (int i = 1; i <= 511; ++i) {                       // alpha'_i uses lq_i
            consume(i, pB, p1, p3);
            float hi1 = __shfl_up_sync(0xffffffffu, a3, 1);
            hi1 = (lane == 0) ? NEG : hi1;
            float n0 = lse2(a0, hi1) + pB;
            float n1 = lse3(a1, a0, hi1 + hsk1) + p1;
            float n2 = lse2(a2, a1) + pB;
            float n3 = lse3(a3, a2, a1 + hsk3) + p3;
            float n4 = lse2(a4, a3) + pB;
            a0 = n0; a1 = n1; a2 = n2; a3 = n3; a4 = n4;
        }
    } else {
        // -------- backward: beta'_1022 .. beta'_511 --------
        float ppB, pp1, pp3;
        consume(0, ppB, pp1, pp3);                             // lq_1023
        if (lane == 31) { a3 = 0.0f; a4 = 0.0f; }              // beta'_1023 init
#pragma unroll 4
        for (int i = 1; i <= 511; ++i) {                       // beta'_{1023-i} uses lq_{1024-i}
            consume(i, pB, p1, p3);
            float c1 = a1 + pp1;
            float c3 = a3 + pp3;
            float cB2 = a2 + ppB;
            float w = c1 + hsk1;
            float wd = __shfl_down_sync(0xffffffffu, w, 1);
            float b0d = __shfl_down_sync(0xffffffffu, a0, 1);
            float t1 = (lane == 31) ? a4 : b0d;
            float t2 = (lane == 31) ? NEG : wd;
            float n0 = lse2(a0 + ppB, c1);
            float n1 = lse3(c1, cB2, c3 + hsk3);
            float n2 = lse2(cB2, c3);
            float n3 = lse3(c3, t1 + ppB, t2);
            float n4 = a4 + ppB;
            a0 = n0; a1 = n1; a2 = n2; a3 = n3; a4 = n4;
            ppB = pB; pp1 = p1; pp3 = p3;
        }
        sbeta[e][4 * lane + 0] = a0;
        sbeta[e][4 * lane + 1] = a1;
        sbeta[e][4 * lane + 2] = a2;
        sbeta[e][4 * lane + 3] = a3;
        if (lane == 31) { sbeta[e][128] = a4; sbeta[e][129] = zAcc; }
    }
    __syncthreads();

    if (fwd) {
        // loglik = (LSE_s(alpha'+beta') - zfwd - zbwd) * ln2
        float c0 = a0 + sbeta[e][4 * lane + 0];
        float c1 = a1 + sbeta[e][4 * lane + 1];
        float c2 = a2 + sbeta[e][4 * lane + 2];
        float c3 = a3 + sbeta[e][4 * lane + 3];
        float c4 = (lane == 31) ? (a4 + sbeta[e][128]) : NEG;
        float m = fmaxf(fmaxf(fmaxf(c0, c1), fmaxf(c2, c3)), c4);
#pragma unroll
        for (int off = 16; off; off >>= 1)
            m = fmaxf(m, __shfl_xor_sync(0xffffffffu, m, off));
        float s = ex2(c0 - m) + ex2(c1 - m) + ex2(c2 - m) + ex2(c3 - m) + ex2(c4 - m);
#pragma unroll
        for (int off = 16; off; off >>= 1)
            s += __shfl_xor_sync(0xffffffffu, s, off);
        if (lane == 0) {
            float loglik = (m + lg2(s) - zAcc - sbeta[e][129]) * LN2_;
            float loss = -loglik;
            float p = expf(-loss);
            float om = 1.0f - p;
            sfocal[e] = 0.25f * om * om * loss;
        }
    }
    __syncthreads();

    // ---- fused mean: last CTA reduces all 256 focal values deterministically ----
    if (threadIdx.x == 0) {
        g_focal[b] = sfocal[0];
        g_focal[b + 1] = sfocal[1];
        __threadfence();
        unsigned int old = atomicAdd(&g_count, 1u);
        sIsLast = (old == gridDim.x - 1) ? 1u : 0u;
    }
    __syncthreads();
    if (sIsLast) {
        float v = g_focal[threadIdx.x] + g_focal[threadIdx.x + 128];
#pragma unroll
        for (int off = 16; off; off >>= 1)
            v += __shfl_xor_sync(0xffffffffu, v, off);
        __shared__ float sm[4];
        if (lane == 0) sm[wid] = v;
        __syncthreads();
        if (threadIdx.x == 0) {
            out[0] = (sm[0] + sm[1] + sm[2] + sm[3]) * (1.0f / (float)B_);
            g_count = 0;                 // reset for next graph replay
        }
    }
}

extern "C" void kernel_launch(void* const* d_in, const int* in_sizes, int n_in,
                              void* d_out, int out_size) {
    const int* y_true;
    const float* y_pred;
    if (in_sizes[0] == B_ * L_) {
        y_true = (const int*)d_in[0];
        y_pred = (const float*)d_in[1];
    } else {
        y_true = (const int*)d_in[1];
        y_pred = (const float*)d_in[0];
    }
    ctc_kernel<<<B_ / 2, 128>>>(y_true, y_pred, (float*)d_out);
}

// round 7
// speedup vs baseline: 9.6246x; 1.9748x over previous
#include <cuda_runtime.h>
#include <math.h>

// FocalCTCLoss: B=256, T=1024, V=128, L=64, S=129, blank=127.
// Log2-domain fp32 CTC DP on UNNORMALIZED lq=lg2(y+eps); softmax normalizer
// Sum_t lg2(Z_t) accumulated as a scalar off the DP path, subtracted at end.
// Forward warp (t=0..511) + backward warp (t=1023..512) per element.
// Round 7: de-spill the prefetch rings — all ring indices are compile-time
// constants (peel-7 + 63x fully-unrolled-8 blocks), launch_bounds(128,1)
// lifts the 64-reg cap. No local memory in the hot loop.

#define B_ 256
#define T_ 1024
#define V_ 128
#define L_ 64
#define EPS_ 1e-7f
#define NEG (-1e30f)
#define LN2_ 0.6931471805599453f

__device__ float g_focal[B_];
__device__ unsigned int g_count;   // zero-init at load; reset by last CTA

__device__ __forceinline__ float ex2(float x) { float r; asm("ex2.approx.ftz.f32 %0,%1;" : "=f"(r) : "f"(x)); return r; }
__device__ __forceinline__ float lg2(float x) { float r; asm("lg2.approx.ftz.f32 %0,%1;" : "=f"(r) : "f"(x)); return r; }

// 2-MUFU LSE2: max + lg2(1 + ex2(min-max))
__device__ __forceinline__ float lse2(float x, float y) {
    float m = fmaxf(x, y), lo = fminf(x, y);
    return m + lg2(1.0f + ex2(lo - m));
}
// 3-MUFU LSE3: the max term contributes ex2(0)=1 exactly
__device__ __forceinline__ float lse3(float x, float y, float z) {
    float mx = fmaxf(x, y), mn = fminf(x, y);
    float m = fmaxf(mx, z);
    float mid = fmaxf(fminf(mx, z), mn);
    float lo = fminf(mn, z);
    return m + lg2(1.0f + ex2(mid - m) + ex2(lo - m));
}

__global__ void __launch_bounds__(128, 1) ctc_kernel(const int* __restrict__ y_true,
                                                     const float* __restrict__ y_pred,
                                                     float* __restrict__ out) {
    __shared__ float sbeta[2][132];      // beta'_511 (129 states) + zbwd at [129]
    __shared__ float sfocal[2];
    __shared__ unsigned int sIsLast;

    const int lane = threadIdx.x & 31;
    const int wid = threadIdx.x >> 5;
    const bool fwd = ((wid & 1) == 0);
    const int e = wid >> 1;
    const int b = (blockIdx.x << 1) + e;

    const float* yb = y_pred + (size_t)b * (T_ * V_);
    const float4* yrow4 = reinterpret_cast<const float4*>(yb);

    // Lane l owns states 4l..4l+3 (lane 31 also s=128).
    //  s=4l: blank  s=4l+1: label 2l  s=4l+2: blank  s=4l+3: label 2l+1
    const int* lr = y_true + b * L_;
    const int lab1 = lr[2 * lane];
    const int lab3 = lr[2 * lane + 1];
    const int labp = (lane > 0) ? lr[2 * lane - 1] : 0;
    const float hsk1 = (lane > 0 && lab1 != labp) ? 0.0f : NEG;  // skip into s=4l+1
    const float hsk3 = (lab3 != lab1) ? 0.0f : NEG;              // skip into s=4l+3

    // iteration i -> timestep t(i) = t0 + dir*i
    const int dir = fwd ? 1 : -1;
    const int t0 = fwd ? 0 : 1023;

    // Register-resident prefetch rings (ALL indices compile-time constants):
    //  rv: float4 rows, depth 8 (feeds Z + blank); g1/g3: label gathers, depth 4.
    float4 rv[8];
    float g1[4], g3[4];
#pragma unroll
    for (int k = 0; k < 8; ++k) rv[k] = yrow4[(t0 + dir * k) * 32 + lane];
#pragma unroll
    for (int k = 0; k < 4; ++k) {
        const float* r = yb + (t0 + dir * k) * V_;
        g1[k] = r[lab1]; g3[k] = r[lab3];
    }

    float zAcc = 0.0f;
    float a0 = NEG, a1 = NEG, a2 = NEG, a3 = NEG, a4 = NEG;
    float pB, p1, p3;
    float ppB, pp1, pp3;

    // consume(i, k): k MUST be a literal constant (= i mod 8) at every call site.
    auto consume = [&](int i, int k, float& oB, float& o1, float& o3) {
        float4 y = rv[k];
        float y1 = g1[k & 3], y3 = g3[k & 3];
        rv[k] = yrow4[(t0 + dir * (i + 8)) * 32 + lane];   // t stays in [0,1023]
        const float* r = yb + (t0 + dir * (i + 4)) * V_;
        g1[k & 3] = r[lab1]; g3[k & 3] = r[lab3];
        float zp = (y.x + y.y) + (y.z + y.w);
        int zi = __reduce_add_sync(0xffffffffu, __float2int_rn(zp * 4194304.0f));
        float Z = (float)zi * (1.0f / 4194304.0f) + (V_ * EPS_);
        zAcc += lg2(Z);                                    // off DP path
        float yB = __shfl_sync(0xffffffffu, y.w, 31);      // y[t][127]
        oB = lg2(yB + EPS_);
        o1 = lg2(y1 + EPS_);
        o3 = lg2(y3 + EPS_);
    };

#define FWD_DP()                                                          \
    {                                                                     \
        float hi1 = __shfl_up_sync(0xffffffffu, a3, 1);                   \
        hi1 = (lane == 0) ? NEG : hi1;                                    \
        float n0 = lse2(a0, hi1) + pB;                                    \
        float n1 = lse3(a1, a0, hi1 + hsk1) + p1;                         \
        float n2 = lse2(a2, a1) + pB;                                     \
        float n3 = lse3(a3, a2, a1 + hsk3) + p3;                          \
        float n4 = lse2(a4, a3) + pB;                                     \
        a0 = n0; a1 = n1; a2 = n2; a3 = n3; a4 = n4;                      \
    }

#define BWD_DP()                                                          \
    {                                                                     \
        float c1 = a1 + pp1;                                              \
        float c3 = a3 + pp3;                                              \
        float cB2 = a2 + ppB;                                             \
        float w = c1 + hsk1;                                              \
        float wd = __shfl_down_sync(0xffffffffu, w, 1);                   \
        float b0d = __shfl_down_sync(0xffffffffu, a0, 1);                 \
        float t1 = (lane == 31) ? a4 : b0d;                               \
        float t2 = (lane == 31) ? NEG : wd;                               \
        float n0 = lse2(a0 + ppB, c1);                                    \
        float n1 = lse3(c1, cB2, c3 + hsk3);                              \
        float n2 = lse2(cB2, c3);                                         \
        float n3 = lse3(c3, t1 + ppB, t2);                                \
        float n4 = a4 + ppB;                                              \
        a0 = n0; a1 = n1; a2 = n2; a3 = n3; a4 = n4;                      \
        ppB = pB; pp1 = p1; pp3 = p3;                                     \
    }

    if (fwd) {
        // -------- forward: alpha'_0 .. alpha'_511 (511 DP steps) --------
        consume(0, 0, pB, p1, p3);
        if (lane == 0) { a0 = pB; a1 = p1; }               // alpha'_0 init
#pragma unroll
        for (int k = 1; k < 8; ++k) {                      // i = 1..7
            consume(k, k, pB, p1, p3);
            FWD_DP();
        }
        for (int ib = 1; ib < 64; ++ib) {                  // i = 8..511
#pragma unroll
            for (int k = 0; k < 8; ++k) {
                consume(ib * 8 + k, k, pB, p1, p3);
                FWD_DP();
            }
        }
    } else {
        // -------- backward: beta'_1022 .. beta'_511 (511 DP steps) --------
        consume(0, 0, ppB, pp1, pp3);                      // lq_1023
        if (lane == 31) { a3 = 0.0f; a4 = 0.0f; }          // beta'_1023 init
#pragma unroll
        for (int k = 1; k < 8; ++k) {                      // i = 1..7
            consume(k, k, pB, p1, p3);
            BWD_DP();
        }
        for (int ib = 1; ib < 64; ++ib) {                  // i = 8..511
#pragma unroll
            for (int k = 0; k < 8; ++k) {
                consume(ib * 8 + k, k, pB, p1, p3);
                BWD_DP();
            }
        }
        sbeta[e][4 * lane + 0] = a0;
        sbeta[e][4 * lane + 1] = a1;
        sbeta[e][4 * lane + 2] = a2;
        sbeta[e][4 * lane + 3] = a3;
        if (lane == 31) { sbeta[e][128] = a4; sbeta[e][129] = zAcc; }
    }
    __syncthreads();

    if (fwd) {
        // loglik = (LSE_s(alpha'+beta') - zfwd - zbwd) * ln2
        float c0 = a0 + sbeta[e][4 * lane + 0];
        float c1 = a1 + sbeta[e][4 * lane + 1];
        float c2 = a2 + sbeta[e][4 * lane + 2];
        float c3 = a3 + sbeta[e][4 * lane + 3];
        float c4 = (lane == 31) ? (a4 + sbeta[e][128]) : NEG;
        float m = fmaxf(fmaxf(fmaxf(c0, c1), fmaxf(c2, c3)), c4);
#pragma unroll
        for (int off = 16; off; off >>= 1)
            m = fmaxf(m, __shfl_xor_sync(0xffffffffu, m, off));
        float s = ex2(c0 - m) + ex2(c1 - m) + ex2(c2 - m) + ex2(c3 - m) + ex2(c4 - m);
#pragma unroll
        for (int off = 16; off; off >>= 1)
            s += __shfl_xor_sync(0xffffffffu, s, off);
        if (lane == 0) {
            float loglik = (m + lg2(s) - zAcc - sbeta[e][129]) * LN2_;
            float loss = -loglik;
            float p = expf(-loss);
            float om = 1.0f - p;
            sfocal[e] = 0.25f * om * om * loss;
        }
    }
    __syncthreads();

    // ---- fused mean: last CTA reduces all 256 focal values deterministically ----
    if (threadIdx.x == 0) {
        g_focal[b] = sfocal[0];
        g_focal[b + 1] = sfocal[1];
        __threadfence();
        unsigned int old = atomicAdd(&g_count, 1u);
        sIsLast = (old == gridDim.x - 1) ? 1u : 0u;
    }
    __syncthreads();
    if (sIsLast) {
        float v = g_focal[threadIdx.x] + g_focal[threadIdx.x + 128];
#pragma unroll
        for (int off = 16; off; off >>= 1)
            v += __shfl_xor_sync(0xffffffffu, v, off);
        __shared__ float sm[4];
        if (lane == 0) sm[wid] = v;
        __syncthreads();
        if (threadIdx.x == 0) {
            out[0] = (sm[0] + sm[1] + sm[2] + sm[3]) * (1.0f / (float)B_);
            g_count = 0;                 // reset for next graph replay
        }
    }
}

extern "C" void kernel_launch(void* const* d_in, const int* in_sizes, int n_in,
                              void* d_out, int out_size) {
    const int* y_true;
    const float* y_pred;
    if (in_sizes[0] == B_ * L_) {
        y_true = (const int*)d_in[0];
        y_pred = (const float*)d_in[1];
    } else {
        y_true = (const int*)d_in[1];
        y_pred = (const float*)d_in[0];
    }
    ctc_kernel<<<B_ / 2, 128>>>(y_true, y_pred, (float*)d_out);
}

// round 8
// speedup vs baseline: 13.7869x; 1.4325x over previous
#include <cuda_runtime.h>
#include <math.h>

// FocalCTCLoss: B=256, T=1024, V=128, L=64, S=129, blank=127.
// Log2-domain fp32 CTC DP on UNNORMALIZED lq=lg2(y+eps); softmax normalizer
// Sum_t lg2(Z_t) computed by DEDICATED Z-warps (warp-specialization), DP
// warps run a pure gather->lg2->LSE recurrence with no warp collectives on
// the critical path (blank via same-address broadcast LDG, not SHFL).
// CTA = 192 threads: w0=fwd e0, w1=bwd e0, w2=fwd e1, w3=bwd e1, w4=Z e0,
// w5=Z e1. Grid 128. Fused last-CTA mean.

#define B_ 256
#define T_ 1024
#define V_ 128
#define L_ 64
#define EPS_ 1e-7f
#define NEG (-1e30f)
#define LN2_ 0.6931471805599453f

__device__ float g_focal[B_];
__device__ unsigned int g_count;   // zero-init at load; reset by last CTA

__device__ __forceinline__ float ex2(float x) { float r; asm("ex2.approx.ftz.f32 %0,%1;" : "=f"(r) : "f"(x)); return r; }
__device__ __forceinline__ float lg2(float x) { float r; asm("lg2.approx.ftz.f32 %0,%1;" : "=f"(r) : "f"(x)); return r; }

// 2-MUFU LSE2: max + lg2(1 + ex2(min-max))
__device__ __forceinline__ float lse2(float x, float y) {
    float m = fmaxf(x, y), lo = fminf(x, y);
    return m + lg2(1.0f + ex2(lo - m));
}
// 3-MUFU LSE3: the max term contributes ex2(0)=1 exactly
__device__ __forceinline__ float lse3(float x, float y, float z) {
    float mx = fmaxf(x, y), mn = fminf(x, y);
    float m = fmaxf(mx, z);
    float mid = fmaxf(fminf(mx, z), mn);
    float lo = fminf(mn, z);
    return m + lg2(1.0f + ex2(mid - m) + ex2(lo - m));
}

__global__ void __launch_bounds__(192, 1) ctc_kernel(const int* __restrict__ y_true,
                                                     const float* __restrict__ y_pred,
                                                     float* __restrict__ out) {
    __shared__ float sbeta[2][132];      // beta'_511 (129 states)
    __shared__ float szTot[2];           // Sum_t lg2(Z_t), t=0..1023
    __shared__ float sfocal[2];
    __shared__ unsigned int sIsLast;

    const int lane = threadIdx.x & 31;
    const int wid = threadIdx.x >> 5;

    if (wid >= 4) {
        // ================= Z-warp: zTot for element e =================
        const int e = wid - 4;
        const int b = (blockIdx.x << 1) + e;
        const float4* yrow4 = reinterpret_cast<const float4*>(y_pred + (size_t)b * (T_ * V_));
        float4 ring[8];
#pragma unroll
        for (int k = 0; k < 8; ++k) ring[k] = yrow4[k * 32 + lane];
        float part[4] = {0.f, 0.f, 0.f, 0.f};
#define ZSTEP(k, refill)                                                      \
        {                                                                     \
            float4 y = ring[k];                                               \
            if (refill) ring[k] = yrow4[(tb * 8 + (k) + 8) * 32 + lane];      \
            float zp = (y.x + y.y) + (y.z + y.w);                             \
            int zi = __reduce_add_sync(0xffffffffu,                           \
                                       __float2int_rn(zp * 4194304.0f));      \
            float Z = (float)zi * (1.0f / 4194304.0f) + (V_ * EPS_);          \
            part[(k) & 3] += lg2(Z);                                          \
        }
        for (int tb = 0; tb < 127; ++tb) {
#pragma unroll
            for (int k = 0; k < 8; ++k) ZSTEP(k, true);
        }
        {
            const int tb = 127; (void)tb;
#pragma unroll
            for (int k = 0; k < 8; ++k) ZSTEP(k, false);
        }
        if (lane == 0) szTot[e] = (part[0] + part[1]) + (part[2] + part[3]);
    } else {
        // ================= DP warp =================
        const bool fwd = ((wid & 1) == 0);
        const int e = wid >> 1;
        const int b = (blockIdx.x << 1) + e;
        const float* yb = y_pred + (size_t)b * (T_ * V_);

        // Lane l owns states 4l..4l+3 (lane 31 also s=128).
        //  s=4l: blank  s=4l+1: label 2l  s=4l+2: blank  s=4l+3: label 2l+1
        const int* lr = y_true + b * L_;
        const int lab1 = lr[2 * lane];
        const int lab3 = lr[2 * lane + 1];
        const int labp = (lane > 0) ? lr[2 * lane - 1] : 0;
        const float hsk1 = (lane > 0 && lab1 != labp) ? 0.0f : NEG;
        const float hsk3 = (lab3 != lab1) ? 0.0f : NEG;

        const int dir = fwd ? 1 : -1;
        const int t0 = fwd ? 0 : 1023;

        // Depth-4 register gather rings (compile-time-constant indices only).
        float gB[4], g1[4], g3[4];
#pragma unroll
        for (int k = 0; k < 4; ++k) {
            const float* r = yb + (t0 + dir * k) * V_;
            gB[k] = r[127]; g1[k] = r[lab1]; g3[k] = r[lab3];
        }

        float a0 = NEG, a1 = NEG, a2 = NEG, a3 = NEG, a4 = NEG;
        float pB, p1, p3, ppB, pp1, pp3;

        // p(0) + refill slot 0 with row for step 4
        pB = lg2(gB[0] + EPS_); p1 = lg2(g1[0] + EPS_); p3 = lg2(g3[0] + EPS_);
        {
            const float* r = yb + (t0 + dir * 4) * V_;
            gB[0] = r[127]; g1[0] = r[lab1]; g3[0] = r[lab3];
        }

        // CONSUME(i,k): k literal == i&3. Produces p for step i; refills i+4.
#define CONSUME(i, k)                                                         \
        {                                                                     \
            float yB = gB[k], y1 = g1[k], y3 = g3[k];                         \
            const float* r = yb + (t0 + dir * ((i) + 4)) * V_;                \
            gB[k] = r[127]; g1[k] = r[lab1]; g3[k] = r[lab3];                 \
            pB = lg2(yB + EPS_); p1 = lg2(y1 + EPS_); p3 = lg2(y3 + EPS_);    \
        }

#define FWD_DP()                                                              \
        {                                                                     \
            float hi1 = __shfl_up_sync(0xffffffffu, a3, 1);                   \
            hi1 = (lane == 0) ? NEG : hi1;                                    \
            float n0 = lse2(a0, hi1) + pB;                                    \
            float n1 = lse3(a1, a0, hi1 + hsk1) + p1;                         \
            float n2 = lse2(a2, a1) + pB;                                     \
            float n3 = lse3(a3, a2, a1 + hsk3) + p3;                          \
            float n4 = lse2(a4, a3) + pB;                                     \
            a0 = n0; a1 = n1; a2 = n2; a3 = n3; a4 = n4;                      \
        }

#define BWD_DP()                                                              \
        {                                                                     \
            float c1 = a1 + pp1;                                              \
            float c3 = a3 + pp3;                                              \
            float cB2 = a2 + ppB;                                             \
            float w = c1 + hsk1;                                              \
            float wd = __shfl_down_sync(0xffffffffu, w, 1);                   \
            float b0d = __shfl_down_sync(0xffffffffu, a0, 1);                 \
            float t1 = (lane == 31) ? a4 : b0d;                               \
            float t2 = (lane == 31) ? NEG : wd;                               \
            float n0 = lse2(a0 + ppB, c1);                                    \
            float n1 = lse3(c1, cB2, c3 + hsk3);                              \
            float n2 = lse2(cB2, c3);                                         \
            float n3 = lse3(c3, t1 + ppB, t2);                                \
            float n4 = a4 + ppB;                                              \
            a0 = n0; a1 = n1; a2 = n2; a3 = n3; a4 = n4;                      \
            ppB = pB; pp1 = p1; pp3 = p3;                                     \
        }

        if (fwd) {
            if (lane == 0) { a0 = pB; a1 = p1; }           // alpha'_0
            CONSUME(1, 1); FWD_DP();
            CONSUME(2, 2); FWD_DP();
            CONSUME(3, 3); FWD_DP();
            for (int ib = 1; ib < 128; ++ib) {             // i = 4..511
                const int base = ib * 4;
                CONSUME(base + 0, 0); FWD_DP();
                CONSUME(base + 1, 1); FWD_DP();
                CONSUME(base + 2, 2); FWD_DP();
                CONSUME(base + 3, 3); FWD_DP();
            }
        } else {
            ppB = pB; pp1 = p1; pp3 = p3;                  // lq_1023
            if (lane == 31) { a3 = 0.0f; a4 = 0.0f; }      // beta'_1023
            CONSUME(1, 1); BWD_DP();
            CONSUME(2, 2); BWD_DP();
            CONSUME(3, 3); BWD_DP();
            for (int ib = 1; ib < 128; ++ib) {             // i = 4..511
                const int base = ib * 4;
                CONSUME(base + 0, 0); BWD_DP();
                CONSUME(base + 1, 1); BWD_DP();
                CONSUME(base + 2, 2); BWD_DP();
                CONSUME(base + 3, 3); BWD_DP();
            }
            sbeta[e][4 * lane + 0] = a0;
            sbeta[e][4 * lane + 1] = a1;
            sbeta[e][4 * lane + 2] = a2;
            sbeta[e][4 * lane + 3] = a3;
            if (lane == 31) sbeta[e][128] = a4;
        }
        __syncthreads();

        if (fwd) {
            // loglik = (LSE_s(alpha'_511 + beta'_511) - zTot) * ln2
            float c0 = a0 + sbeta[e][4 * lane + 0];
            float c1 = a1 + sbeta[e][4 * lane + 1];
            float c2 = a2 + sbeta[e][4 * lane + 2];
            float c3 = a3 + sbeta[e][4 * lane + 3];
            float c4 = (lane == 31) ? (a4 + sbeta[e][128]) : NEG;
            float m = fmaxf(fmaxf(fmaxf(c0, c1), fmaxf(c2, c3)), c4);
#pragma unroll
            for (int off = 16; off; off >>= 1)
                m = fmaxf(m, __shfl_xor_sync(0xffffffffu, m, off));
            float s = ex2(c0 - m) + ex2(c1 - m) + ex2(c2 - m) + ex2(c3 - m) + ex2(c4 - m);
#pragma unroll
            for (int off = 16; off; off >>= 1)
                s += __shfl_xor_sync(0xffffffffu, s, off);
            if (lane == 0) {
                float loglik = (m + lg2(s) - szTot[e]) * LN2_;
                float loss = -loglik;
                float p = expf(-loss);
                float om = 1.0f - p;
                sfocal[e] = 0.25f * om * om * loss;
            }
        }
    }
    __syncthreads();

    // ---- fused mean: last CTA reduces all 256 focal values deterministically ----
    if (threadIdx.x == 0) {
        const int b0 = blockIdx.x << 1;
        g_focal[b0] = sfocal[0];
        g_focal[b0 + 1] = sfocal[1];
        __threadfence();
        unsigned int old = atomicAdd(&g_count, 1u);
        sIsLast = (old == gridDim.x - 1) ? 1u : 0u;
    }
    __syncthreads();
    if (sIsLast && threadIdx.x < 128) {
        float v = g_focal[threadIdx.x] + g_focal[threadIdx.x + 128];
#pragma unroll
        for (int off = 16; off; off >>= 1)
            v += __shfl_xor_sync(0xffffffffu, v, off);
        __shared__ float sm[4];
        if (lane == 0) sm[wid] = v;
        __syncwarp();
        if (threadIdx.x == 0) {
            // warps 0-3 all hit the smem write above before this read only if
            // we sync the first 128 threads; use a full-block path instead:
            // (sm writes happen pre-read because warp 0 reads after its own
            // write; cross-warp ordering enforced below)
        }
    }
    __syncthreads();
    if (sIsLast && threadIdx.x == 0) {
        __shared__ float smDummy;  // keep compiler happy about sm scope
        (void)smDummy;
        extern __shared__ float _noop[];  // unused
        float total = 0.f;
        // re-read the 4 per-warp partials via g_focal-free path: recompute from sm
        // NOTE: sm[] is function-scope static shared; redeclare accessor:
        total = 0.f;
        {
            // sm was declared in the guarded block; hoist logic: recompute here
        }
        // fallback: direct serial sum of 256 values (256 FADD, ~1us, last CTA only)
        float acc = 0.f;
#pragma unroll 8
        for (int i = 0; i < B_; ++i) acc += g_focal[i];
        out[0] = acc * (1.0f / (float)B_);
        g_count = 0;                 // reset for next graph replay
    }
}

extern "C" void kernel_launch(void* const* d_in, const int* in_sizes, int n_in,
                              void* d_out, int out_size) {
    const int* y_true;
    const float* y_pred;
    if (in_sizes[0] == B_ * L_) {
        y_true = (const int*)d_in[0];
        y_pred = (const float*)d_in[1];
    } else {
        y_true = (const int*)d_in[1];
        y_pred = (const float*)d_in[0];
    }
    ctc_kernel<<<B_ / 2, 192>>>(y_true, y_pred, (float*)d_out);
}

// round 9
// speedup vs baseline: 14.2471x; 1.0334x over previous
#include <cuda_runtime.h>
#include <math.h>

// FocalCTCLoss: B=256, T=1024, V=128, L=64, S=129, blank=127.
// LINEAR-domain fp32 CTC DP with exact per-lane power-of-2 rescaling
// (no MUFU in the hot loop). Multipliers are unnormalized q = y+eps; the
// softmax normalizer Sum_t lg2(Z_t) comes from dedicated Z-warps (szTot).
// Per lane: true alpha = a * 2^K (K int). Renorm every 4 steps: K absorbs
// the exponent of the lane max (exact). Cross-lane SHFL values adjusted by
// one FMUL with 2^(Kn-K) (exact). Fwd warp t=0..511, bwd warp t=1023..512;
// combine in log2 domain at the end. Grid 128 x 192 (4 DP + 2 Z warps).

#define B_ 256
#define T_ 1024
#define V_ 128
#define L_ 64
#define EPS_ 1e-7f
#define NEG (-1e30f)
#define LN2_ 0.6931471805599453f

__device__ float g_focal[B_];
__device__ unsigned int g_count;   // zero-init at load; reset by last CTA

__device__ __forceinline__ float ex2(float x) { float r; asm("ex2.approx.ftz.f32 %0,%1;" : "=f"(r) : "f"(x)); return r; }
__device__ __forceinline__ float lg2(float x) { float r; asm("lg2.approx.ftz.f32 %0,%1;" : "=f"(r) : "f"(x)); return r; }

__global__ void __launch_bounds__(192, 1) ctc_kernel(const int* __restrict__ y_true,
                                                     const float* __restrict__ y_pred,
                                                     float* __restrict__ out) {
    __shared__ float sbeta[2][132];      // bwd log2(beta') per state (129)
    __shared__ float szTot[2];           // Sum_t lg2(Z_t)
    __shared__ float sfocal[2];
    __shared__ float sred[4];
    __shared__ unsigned int sIsLast;

    const int lane = threadIdx.x & 31;
    const int wid = threadIdx.x >> 5;

    if (wid >= 4) {
        // ================= Z-warp: szTot for element e =================
        const int e = wid - 4;
        const int b = (blockIdx.x << 1) + e;
        const float4* yrow4 = reinterpret_cast<const float4*>(y_pred + (size_t)b * (T_ * V_));
        float4 ring[8];
#pragma unroll
        for (int k = 0; k < 8; ++k) ring[k] = yrow4[k * 32 + lane];
        float part[4] = {0.f, 0.f, 0.f, 0.f};
#define ZSTEP(k, refill)                                                      \
        {                                                                     \
            float4 y = ring[k];                                               \
            if (refill) ring[k] = yrow4[(tb * 8 + (k) + 8) * 32 + lane];      \
            float zp = (y.x + y.y) + (y.z + y.w);                             \
            int zi = __reduce_add_sync(0xffffffffu,                           \
                                       __float2int_rn(zp * 4194304.0f));      \
            float Z = (float)zi * (1.0f / 4194304.0f) + (V_ * EPS_);          \
            part[(k) & 3] += lg2(Z);                                          \
        }
        for (int tb = 0; tb < 127; ++tb) {
#pragma unroll
            for (int k = 0; k < 8; ++k) ZSTEP(k, true);
        }
        {
            const int tb = 127; (void)tb;
#pragma unroll
            for (int k = 0; k < 8; ++k) ZSTEP(k, false);
        }
        if (lane == 0) szTot[e] = (part[0] + part[1]) + (part[2] + part[3]);
    } else {
        // ================= DP warp (linear domain) =================
        const bool fwd = ((wid & 1) == 0);
        const int e = wid >> 1;
        const int b = (blockIdx.x << 1) + e;
        const float* yb = y_pred + (size_t)b * (T_ * V_);

        // Lane l owns states 4l..4l+3 (lane 31 also s=128).
        //  s=4l: blank  s=4l+1: label 2l  s=4l+2: blank  s=4l+3: label 2l+1
        const int* lr = y_true + b * L_;
        const int lab1 = lr[2 * lane];
        const int lab3 = lr[2 * lane + 1];
        const int labp = (lane > 0) ? lr[2 * lane - 1] : 0;
        const float sk1 = (lane > 0 && lab1 != labp) ? 1.0f : 0.0f;
        const float sk3 = (lab3 != lab1) ? 1.0f : 0.0f;

        const int dir = fwd ? 1 : -1;
        const int t0 = fwd ? 0 : 1023;
        const int edge = fwd ? 0 : 31;

        // Depth-8 register gather rings (compile-time-constant indices only).
        float gB[8], g1[8], g3[8];
#pragma unroll
        for (int k = 0; k < 8; ++k) {
            const float* r = yb + (t0 + dir * k) * V_;
            gB[k] = r[127]; g1[k] = r[lab1]; g3[k] = r[lab3];
        }

        float a0 = 0.f, a1 = 0.f, a2 = 0.f, a3 = 0.f, a4 = 0.f;
        int K = 0;
        float sc = (lane == edge) ? 0.0f : 1.0f;   // 2^(Kn-K); 0 kills edge input
        float qB, q1, q3, pqB, pq1, pq3;

        // CONSUME(i,k): k literal == i&7. q for step i; refill slot with i+8.
#define CONSUME(i, k)                                                         \
        {                                                                     \
            qB = gB[k] + EPS_; q1 = g1[k] + EPS_; q3 = g3[k] + EPS_;          \
            const float* r = yb + (t0 + dir * ((i) + 8)) * V_;                \
            gB[k] = r[127]; g1[k] = r[lab1]; g3[k] = r[lab3];                 \
        }

        // RENORM: exact power-of-2 rescale; recompute neighbor scale factor.
#define RENORM(SHFL_EXPR)                                                     \
        {                                                                     \
            float m = fmaxf(fmaxf(fmaxf(a0, a1), fmaxf(a2, a3)), a4);         \
            int ee = (int)(__float_as_uint(m) >> 23);                         \
            int ec = (ee > 0) ? ee : 127;                                     \
            K += ec - 127;                                                    \
            float rsc = __int_as_float((unsigned)(254 - ec) << 23);           \
            a0 *= rsc; a1 *= rsc; a2 *= rsc; a3 *= rsc; a4 *= rsc;            \
            int Kn = SHFL_EXPR;                                               \
            int d = Kn - K; if (d > 127) d = 127;                             \
            sc = (d < -126) ? 0.0f : __int_as_float((unsigned)(d + 127) << 23); \
            if (lane == edge) sc = 0.0f;                                      \
        }

#define FWD_DP()                                                              \
        {                                                                     \
            float hi1 = __shfl_up_sync(0xffffffffu, a3, 1) * sc;              \
            float n0 = (a0 + hi1) * qB;                                       \
            float n1 = fmaf(sk1, hi1, a0 + a1) * q1;                          \
            float n2 = (a1 + a2) * qB;                                        \
            float n3 = fmaf(sk3, a1, a2 + a3) * q3;                           \
            float n4 = (a3 + a4) * qB;                                        \
            a0 = n0; a1 = n1; a2 = n2; a3 = n3;                               \
            a4 = (lane == 31) ? n4 : 0.0f;                                    \
        }

#define BWD_DP()                                                              \
        {                                                                     \
            float c1 = a1 * pq1;                                              \
            float c3 = a3 * pq3;                                              \
            float cB2 = a2 * pqB;                                             \
            float w = c1 * sk1;                                               \
            float wd = __shfl_down_sync(0xffffffffu, w, 1) * sc;              \
            float b0d = __shfl_down_sync(0xffffffffu, a0, 1) * sc;            \
            float t1 = (lane == 31) ? a4 : b0d;                               \
            float t2 = (lane == 31) ? 0.0f : wd;                              \
            float n0 = fmaf(a0, pqB, c1);                                     \
            float n1 = fmaf(c3, sk3, c1 + cB2);                               \
            float n2 = cB2 + c3;                                              \
            float n3 = fmaf(t1, pqB, c3 + t2);                                \
            float n4 = a4 * pqB;                                              \
            a0 = n0; a1 = n1; a2 = n2; a3 = n3; a4 = n4;                      \
            pqB = qB; pq1 = q1; pq3 = q3;                                     \
        }

#define SH_UP   __shfl_up_sync(0xffffffffu, K, 1)
#define SH_DN   __shfl_down_sync(0xffffffffu, K, 1)

        if (fwd) {
            CONSUME(0, 0);
            if (lane == 0) { a0 = qB; a1 = q1; }           // alpha'_0
#pragma unroll
            for (int i = 1; i < 8; ++i) {                  // peel i=1..7
                switch (i) {  // keep slot literal
                    case 1: CONSUME(1, 1); break; case 2: CONSUME(2, 2); break;
                    case 3: CONSUME(3, 3); break; case 4: CONSUME(4, 4); break;
                    case 5: CONSUME(5, 5); break; case 6: CONSUME(6, 6); break;
                    case 7: CONSUME(7, 7); break;
                }
                FWD_DP();
                if ((i & 3) == 3) RENORM(SH_UP);
            }
            for (int ib = 1; ib < 64; ++ib) {              // i = 8..511
                const int base = ib * 8;
                CONSUME(base + 0, 0); FWD_DP();
                CONSUME(base + 1, 1); FWD_DP();
                CONSUME(base + 2, 2); FWD_DP();
                CONSUME(base + 3, 3); FWD_DP(); RENORM(SH_UP);
                CONSUME(base + 4, 4); FWD_DP();
                CONSUME(base + 5, 5); FWD_DP();
                CONSUME(base + 6, 6); FWD_DP();
                CONSUME(base + 7, 7); FWD_DP(); RENORM(SH_UP);
            }
        } else {
            CONSUME(0, 0);
            pqB = qB; pq1 = q1; pq3 = q3;                  // q(1023)
            if (lane == 31) { a3 = 1.0f; a4 = 1.0f; }      // beta_1023
#pragma unroll
            for (int i = 1; i < 8; ++i) {                  // peel i=1..7
                switch (i) {
                    case 1: CONSUME(1, 1); break; case 2: CONSUME(2, 2); break;
                    case 3: CONSUME(3, 3); break; case 4: CONSUME(4, 4); break;
                    case 5: CONSUME(5, 5); break; case 6: CONSUME(6, 6); break;
                    case 7: CONSUME(7, 7); break;
                }
                BWD_DP();
                if ((i & 3) == 3) RENORM(SH_DN);
            }
            for (int ib = 1; ib < 64; ++ib) {              // i = 8..511
                const int base = ib * 8;
                CONSUME(base + 0, 0); BWD_DP();
                CONSUME(base + 1, 1); BWD_DP();
                CONSUME(base + 2, 2); BWD_DP();
                CONSUME(base + 3, 3); BWD_DP(); RENORM(SH_DN);
                CONSUME(base + 4, 4); BWD_DP();
                CONSUME(base + 5, 5); BWD_DP();
                CONSUME(base + 6, 6); BWD_DP();
                CONSUME(base + 7, 7); BWD_DP(); RENORM(SH_DN);
            }
            float Kf = (float)K;
            sbeta[e][4 * lane + 0] = lg2(a0) + Kf;
            sbeta[e][4 * lane + 1] = lg2(a1) + Kf;
            sbeta[e][4 * lane + 2] = lg2(a2) + Kf;
            sbeta[e][4 * lane + 3] = lg2(a3) + Kf;
            if (lane == 31) sbeta[e][128] = lg2(a4) + Kf;
        }
        __syncthreads();

        if (fwd) {
            // loglik = (LSE_s(log2 alpha'_511 + log2 beta'_511) - szTot)*ln2
            float Kf = (float)K;
            float c0 = lg2(a0) + Kf + sbeta[e][4 * lane + 0];
            float c1 = lg2(a1) + Kf + sbeta[e][4 * lane + 1];
            float c2 = lg2(a2) + Kf + sbeta[e][4 * lane + 2];
            float c3 = lg2(a3) + Kf + sbeta[e][4 * lane + 3];
            float c4 = (lane == 31) ? (lg2(a4) + Kf + sbeta[e][128]) : NEG;
            float m = fmaxf(fmaxf(fmaxf(c0, c1), fmaxf(c2, c3)), c4);
#pragma unroll
            for (int off = 16; off; off >>= 1)
                m = fmaxf(m, __shfl_xor_sync(0xffffffffu, m, off));
            float s = ex2(c0 - m) + ex2(c1 - m) + ex2(c2 - m) + ex2(c3 - m) + ex2(c4 - m);
#pragma unroll
            for (int off = 16; off; off >>= 1)
                s += __shfl_xor_sync(0xffffffffu, s, off);
            if (lane == 0) {
                float loglik = (m + lg2(s) - szTot[e]) * LN2_;
                float loss = -loglik;
                float p = expf(-loss);
                float om = 1.0f - p;
                sfocal[e] = 0.25f * om * om * loss;
            }
        }
    }
    __syncthreads();

    // ---- fused mean: last CTA reduces all 256 focal values in parallel ----
    if (threadIdx.x == 0) {
        const int b0 = blockIdx.x << 1;
        g_focal[b0] = sfocal[0];
        g_focal[b0 + 1] = sfocal[1];
        __threadfence();
        unsigned int old = atomicAdd(&g_count, 1u);
        sIsLast = (old == gridDim.x - 1) ? 1u : 0u;
    }
    __syncthreads();
    if (sIsLast && threadIdx.x < 128) {
        float v = g_focal[threadIdx.x] + g_focal[threadIdx.x + 128];
#pragma unroll
        for (int off = 16; off; off >>= 1)
            v += __shfl_xor_sync(0xffffffffu, v, off);
        if (lane == 0) sred[wid] = v;
    }
    __syncthreads();
    if (sIsLast && threadIdx.x == 0) {
        out[0] = ((sred[0] + sred[1]) + (sred[2] + sred[3])) * (1.0f / (float)B_);
        g_count = 0;                 // reset for next graph replay
    }
}

extern "C" void kernel_launch(void* const* d_in, const int* in_sizes, int n_in,
                              void* d_out, int out_size) {
    const int* y_true;
    const float* y_pred;
    if (in_sizes[0] == B_ * L_) {
        y_true = (const int*)d_in[0];
        y_pred = (const float*)d_in[1];
    } else {
        y_true = (const int*)d_in[1];
        y_pred = (const float*)d_in[0];
    }
    ctc_kernel<<<B_ / 2, 192>>>(y_true, y_pred, (float*)d_out);
}

// round 10
// speedup vs baseline: 20.3517x; 1.4285x over previous
#include <cuda_runtime.h>
#include <math.h>

// FocalCTCLoss: B=256, T=1024, V=128, L=64, S=129, blank=127.
// LINEAR-domain fp32 CTC DP with exact power-of-2 rescaling (no MUFU in DP).
// Each DP warp is self-sufficient: coalesced float4 row loads -> private
// double-buffered smem staging (8-row blocks) -> label gathers via LDS
// (crossbar scatter, no L1tex wavefront storm) -> Z row-partials from the
// same staged data, summed via conflict-free transposed smem every 16 rows.
// No REDUX, no Z-warps, each y_pred row read exactly once, coalesced.
// CTA = 128 thr: w0=fwd e0, w1=bwd e0, w2=fwd e1, w3=bwd e1. Grid 128.

#define B_ 256
#define T_ 1024
#define V_ 128
#define L_ 64
#define EPS_ 1e-7f
#define NEG (-1e30f)
#define LN2_ 0.6931471805599453f

__device__ float g_focal[B_];
__device__ unsigned int g_count;   // zero-init at load; reset by last CTA

__device__ __forceinline__ float ex2(float x) { float r; asm("ex2.approx.ftz.f32 %0,%1;" : "=f"(r) : "f"(x)); return r; }
__device__ __forceinline__ float lg2(float x) { float r; asm("lg2.approx.ftz.f32 %0,%1;" : "=f"(r) : "f"(x)); return r; }

__global__ void __launch_bounds__(128, 1) ctc_kernel(const int* __restrict__ y_true,
                                                     const float* __restrict__ y_pred,
                                                     float* __restrict__ out) {
    __shared__ float4 sstage4[4][2][8][32];   // [warp][buf][row][lane] 32KB
    __shared__ float szp[4][16][33];          // Z row-partials (transposed sum)
    __shared__ float sbeta[2][132];           // bwd log2(beta') per state
    __shared__ float szHalf[4];               // per-warp Sum lg2(Z) halves
    __shared__ float sfocal[2];
    __shared__ float sred[4];
    __shared__ unsigned int sIsLast;

    const int lane = threadIdx.x & 31;
    const int wid = threadIdx.x >> 5;
    const bool fwd = ((wid & 1) == 0);
    const int e = wid >> 1;
    const int b = (blockIdx.x << 1) + e;

    const float4* yrow4 = reinterpret_cast<const float4*>(y_pred + (size_t)b * (T_ * V_));

    // Lane l owns states 4l..4l+3 (lane 31 also s=128).
    //  s=4l: blank  s=4l+1: label 2l  s=4l+2: blank  s=4l+3: label 2l+1
    const int* lr = y_true + b * L_;
    const int lab1 = lr[2 * lane];
    const int lab3 = lr[2 * lane + 1];
    const int labp = (lane > 0) ? lr[2 * lane - 1] : 0;
    const float sk1 = (lane > 0 && lab1 != labp) ? 1.0f : 0.0f;
    const float sk3 = (lab3 != lab1) ? 1.0f : 0.0f;

    const int dir = fwd ? 1 : -1;
    const int t0 = fwd ? 0 : 1023;
    const int edge = fwd ? 0 : 31;

    float* const sstW = reinterpret_cast<float*>(&sstage4[wid][0][0][0]);

    float4 rv[8];                       // register row ring for next block
#pragma unroll
    for (int r = 0; r < 8; ++r) rv[r] = yrow4[(t0 + dir * r) * 32 + lane];

    float a0 = 0.f, a1 = 0.f, a2 = 0.f, a3 = 0.f, a4 = 0.f;
    int K = 0;
    float sc = (lane == edge) ? 0.0f : 1.0f;
    float qB, q1, q3, pqB, pq1, pq3;
    float zpart = 0.f;

    // ---- stage block c: STS 8 rows + Z partials, then syncwarp ----
#define STAGE8(c)                                                             \
    {                                                                         \
        float4* dst = reinterpret_cast<float4*>(sst);                         \
        _Pragma("unroll")                                                     \
        for (int r = 0; r < 8; ++r) {                                         \
            float4 y = rv[r];                                                 \
            dst[r * 32 + lane] = y;                                           \
            szp[wid][((c) * 8 + r) & 15][lane] = (y.x + y.y) + (y.z + y.w);   \
        }                                                                     \
        __syncwarp();                                                         \
    }

#define PREFETCH8(c)                                                          \
    {                                                                         \
        _Pragma("unroll")                                                     \
        for (int r = 0; r < 8; ++r)                                           \
            rv[r] = yrow4[(t0 + dir * (((c) + 1) * 8 + r)) * 32 + lane];      \
    }

    // ---- transposed Z sum over 16 completed rows (conflict-free) ----
#define TRANSPOSE_Z()                                                         \
    {                                                                         \
        int rr = lane & 15;                                                   \
        int j0 = (lane >> 4) << 4;                                            \
        float Zs0 = 0.f, Zs1 = 0.f;                                           \
        _Pragma("unroll")                                                     \
        for (int j = 0; j < 16; j += 2) {                                     \
            Zs0 += szp[wid][rr][j0 + j];                                      \
            Zs1 += szp[wid][rr][j0 + j + 1];                                  \
        }                                                                     \
        float Zs = Zs0 + Zs1;                                                 \
        Zs += __shfl_down_sync(0xffffffffu, Zs, 16);                          \
        if (lane < 16) zpart += lg2(Zs + V_ * EPS_);                          \
        __syncwarp();                                                         \
    }

#define QLDS(r)                                                               \
    {                                                                         \
        const float* rw = sst + (r) * 128;                                    \
        qB = rw[127] + EPS_; q1 = rw[lab1] + EPS_; q3 = rw[lab3] + EPS_;      \
    }

#define RENORM(SHFL_EXPR)                                                     \
    {                                                                         \
        float m = fmaxf(fmaxf(fmaxf(a0, a1), fmaxf(a2, a3)), a4);             \
        int ee = (int)(__float_as_uint(m) >> 23);                             \
        int ec = (ee > 0) ? ee : 127;                                         \
        K += ec - 127;                                                        \
        float rsc = __int_as_float((unsigned)(254 - ec) << 23);               \
        a0 *= rsc; a1 *= rsc; a2 *= rsc; a3 *= rsc; a4 *= rsc;                \
        int Kn = SHFL_EXPR;                                                   \
        int d = Kn - K; if (d > 127) d = 127;                                 \
        sc = (d < -126) ? 0.0f : __int_as_float((unsigned)(d + 127) << 23);   \
        if (lane == edge) sc = 0.0f;                                          \
    }

#define FWD_DP()                                                              \
    {                                                                         \
        float hi1 = __shfl_up_sync(0xffffffffu, a3, 1) * sc;                  \
        float n0 = (a0 + hi1) * qB;                                           \
        float n1 = fmaf(sk1, hi1, a0 + a1) * q1;                              \
        float n2 = (a1 + a2) * qB;                                            \
        float n3 = fmaf(sk3, a1, a2 + a3) * q3;                               \
        float n4 = (a3 + a4) * qB;                                            \
        a0 = n0; a1 = n1; a2 = n2; a3 = n3;                                   \
        a4 = (lane == 31) ? n4 : 0.0f;                                        \
    }

#define BWD_DP()                                                              \
    {                                                                         \
        float c1 = a1 * pq1;                                                  \
        float c3 = a3 * pq3;                                                  \
        float cB2 = a2 * pqB;                                                 \
        float w = c1 * sk1;                                                   \
        float wd = __shfl_down_sync(0xffffffffu, w, 1) * sc;                  \
        float b0d = __shfl_down_sync(0xffffffffu, a0, 1) * sc;                \
        float t1 = (lane == 31) ? a4 : b0d;                                   \
        float t2 = (lane == 31) ? 0.0f : wd;                                  \
        float n0 = fmaf(a0, pqB, c1);                                         \
        float n1 = fmaf(c3, sk3, c1 + cB2);                                   \
        float n2 = cB2 + c3;                                                  \
        float n3 = fmaf(t1, pqB, c3 + t2);                                    \
        float n4 = a4 * pqB;                                                  \
        a0 = n0; a1 = n1; a2 = n2; a3 = n3; a4 = n4;                          \
        pqB = qB; pq1 = q1; pq3 = q3;                                         \
    }

#define SH_UP   __shfl_up_sync(0xffffffffu, K, 1)
#define SH_DN   __shfl_down_sync(0xffffffffu, K, 1)

#define FWD_BLOCK(c, PF)                                                      \
    {                                                                         \
        float* sst = sstW + ((c) & 1) * 1024;                                 \
        STAGE8(c);                                                            \
        if (PF) PREFETCH8(c);                                                 \
        QLDS(0); FWD_DP();                                                    \
        QLDS(1); FWD_DP();                                                    \
        QLDS(2); FWD_DP();                                                    \
        QLDS(3); FWD_DP(); RENORM(SH_UP);                                     \
        QLDS(4); FWD_DP();                                                    \
        QLDS(5); FWD_DP();                                                    \
        QLDS(6); FWD_DP();                                                    \
        QLDS(7); FWD_DP(); RENORM(SH_UP);                                     \
    }

#define BWD_BLOCK(c, PF)                                                      \
    {                                                                         \
        float* sst = sstW + ((c) & 1) * 1024;                                 \
        STAGE8(c);                                                            \
        if (PF) PREFETCH8(c);                                                 \
        QLDS(0); BWD_DP();                                                    \
        QLDS(1); BWD_DP();                                                    \
        QLDS(2); BWD_DP();                                                    \
        QLDS(3); BWD_DP(); RENORM(SH_DN);                                     \
        QLDS(4); BWD_DP();                                                    \
        QLDS(5); BWD_DP();                                                    \
        QLDS(6); BWD_DP();                                                    \
        QLDS(7); BWD_DP(); RENORM(SH_DN);                                     \
    }

    if (fwd) {
        {   // block 0: step 0 is init, steps 1..7 DP
            float* sst = sstW;
            STAGE8(0);
            PREFETCH8(0);
            QLDS(0);
            if (lane == 0) { a0 = qB; a1 = q1; }            // alpha'_0
            QLDS(1); FWD_DP();
            QLDS(2); FWD_DP();
            QLDS(3); FWD_DP(); RENORM(SH_UP);
            QLDS(4); FWD_DP();
            QLDS(5); FWD_DP();
            QLDS(6); FWD_DP();
            QLDS(7); FWD_DP(); RENORM(SH_UP);
        }
        for (int cp = 0; cp < 31; ++cp) {                   // blocks 1..62
            const int c = 2 * cp + 1;
            FWD_BLOCK(c, true); TRANSPOSE_Z();
            FWD_BLOCK(c + 1, true);
        }
        FWD_BLOCK(63, false); TRANSPOSE_Z();
    } else {
        {   // block 0: step 0 loads q(1023) into pq + init, steps 1..7 DP
            float* sst = sstW;
            STAGE8(0);
            PREFETCH8(0);
            QLDS(0);
            pqB = qB; pq1 = q1; pq3 = q3;
            if (lane == 31) { a3 = 1.0f; a4 = 1.0f; }       // beta_1023
            QLDS(1); BWD_DP();
            QLDS(2); BWD_DP();
            QLDS(3); BWD_DP(); RENORM(SH_DN);
            QLDS(4); BWD_DP();
            QLDS(5); BWD_DP();
            QLDS(6); BWD_DP();
            QLDS(7); BWD_DP(); RENORM(SH_DN);
        }
        for (int cp = 0; cp < 31; ++cp) {                   // blocks 1..62
            const int c = 2 * cp + 1;
            BWD_BLOCK(c, true); TRANSPOSE_Z();
            BWD_BLOCK(c + 1, true);
        }
        BWD_BLOCK(63, false); TRANSPOSE_Z();
    }

    // per-warp Sum lg2(Z) over its 512 timesteps (lanes >=16 hold 0)
#pragma unroll
    for (int off = 16; off; off >>= 1)
        zpart += __shfl_xor_sync(0xffffffffu, zpart, off);
    if (lane == 0) szHalf[wid] = zpart;

    if (!fwd) {
        float Kf = (float)K;
        sbeta[e][4 * lane + 0] = lg2(a0) + Kf;
        sbeta[e][4 * lane + 1] = lg2(a1) + Kf;
        sbeta[e][4 * lane + 2] = lg2(a2) + Kf;
        sbeta[e][4 * lane + 3] = lg2(a3) + Kf;
        if (lane == 31) sbeta[e][128] = lg2(a4) + Kf;
    }
    __syncthreads();

    if (fwd) {
        // loglik = (LSE_s(log2 alpha'_511 + log2 beta'_511) - szTot) * ln2
        float Kf = (float)K;
        float c0 = lg2(a0) + Kf + sbeta[e][4 * lane + 0];
        float c1 = lg2(a1) + Kf + sbeta[e][4 * lane + 1];
        float c2 = lg2(a2) + Kf + sbeta[e][4 * lane + 2];
        float c3 = lg2(a3) + Kf + sbeta[e][4 * lane + 3];
        float c4 = (lane == 31) ? (lg2(a4) + Kf + sbeta[e][128]) : NEG;
        float m = fmaxf(fmaxf(fmaxf(c0, c1), fmaxf(c2, c3)), c4);
#pragma unroll
        for (int off = 16; off; off >>= 1)
            m = fmaxf(m, __shfl_xor_sync(0xffffffffu, m, off));
        float s = ex2(c0 - m) + ex2(c1 - m) + ex2(c2 - m) + ex2(c3 - m) + ex2(c4 - m);
#pragma unroll
        for (int off = 16; off; off >>= 1)
            s += __shfl_xor_sync(0xffffffffu, s, off);
        if (lane == 0) {
            float szTot = szHalf[wid] + szHalf[wid + 1];
            float loglik = (m + lg2(s) - szTot) * LN2_;
            float loss = -loglik;
            float p = expf(-loss);
            float om = 1.0f - p;
            sfocal[e] = 0.25f * om * om * loss;
        }
    }
    __syncthreads();

    // ---- fused mean: last CTA reduces all 256 focal values in parallel ----
    if (threadIdx.x == 0) {
        const int b0 = blockIdx.x << 1;
        g_focal[b0] = sfocal[0];
        g_focal[b0 + 1] = sfocal[1];
        __threadfence();
        unsigned int old = atomicAdd(&g_count, 1u);
        sIsLast = (old == gridDim.x - 1) ? 1u : 0u;
    }
    __syncthreads();
    if (sIsLast) {
        float v = g_focal[threadIdx.x] + g_focal[threadIdx.x + 128];
#pragma unroll
        for (int off = 16; off; off >>= 1)
            v += __shfl_xor_sync(0xffffffffu, v, off);
        if (lane == 0) sred[wid] = v;
        __syncthreads();
        if (threadIdx.x == 0) {
            out[0] = ((sred[0] + sred[1]) + (sred[2] + sred[3])) * (1.0f / (float)B_);
            g_count = 0;             // reset for next graph replay
        }
    }
}

extern "C" void kernel_launch(void* const* d_in, const int* in_sizes, int n_in,
                              void* d_out, int out_size) {
    const int* y_true;
    const float* y_pred;
    if (in_sizes[0] == B_ * L_) {
        y_true = (const int*)d_in[0];
        y_pred = (const float*)d_in[1];
    } else {
        y_true = (const int*)d_in[1];
        y_pred = (const float*)d_in[0];
    }
    ctc_kernel<<<B_ / 2, 128>>>(y_true, y_pred, (float*)d_out);
}

// round 11
// speedup vs baseline: 21.0827x; 1.0359x over previous
#include <cuda_runtime.h>
#include <math.h>

// FocalCTCLoss: B=256, T=1024, V=128, L=64, S=129, blank=127.
// LINEAR-domain fp32 CTC DP with exact power-of-2 rescaling (no MUFU in DP).
// Coalesced float4 row loads -> double-buffered smem staging (8-row blocks)
// -> label gathers via LDS. Z from staged data via transposed smem sums.
// R11: forward q-loads software-pipelined one step ahead (cur/nxt rotation,
// kills the per-step exposed LDS); RENORM once per 8-row block.
// CTA = 128 thr: w0=fwd e0, w1=bwd e0, w2=fwd e1, w3=bwd e1. Grid 128.

#define B_ 256
#define T_ 1024
#define V_ 128
#define L_ 64
#define EPS_ 1e-7f
#define NEG (-1e30f)
#define LN2_ 0.6931471805599453f

__device__ float g_focal[B_];
__device__ unsigned int g_count;   // zero-init at load; reset by last CTA

__device__ __forceinline__ float ex2(float x) { float r; asm("ex2.approx.ftz.f32 %0,%1;" : "=f"(r) : "f"(x)); return r; }
__device__ __forceinline__ float lg2(float x) { float r; asm("lg2.approx.ftz.f32 %0,%1;" : "=f"(r) : "f"(x)); return r; }

__global__ void __launch_bounds__(128, 1) ctc_kernel(const int* __restrict__ y_true,
                                                     const float* __restrict__ y_pred,
                                                     float* __restrict__ out) {
    __shared__ float4 sstage4[4][2][8][32];   // [warp][buf][row][lane] 32KB
    __shared__ float szp[4][16][33];          // Z row-partials (transposed sum)
    __shared__ float sbeta[2][132];           // bwd log2(beta') per state
    __shared__ float szHalf[4];               // per-warp Sum lg2(Z) halves
    __shared__ float sfocal[2];
    __shared__ float sred[4];
    __shared__ unsigned int sIsLast;

    const int lane = threadIdx.x & 31;
    const int wid = threadIdx.x >> 5;
    const bool fwd = ((wid & 1) == 0);
    const int e = wid >> 1;
    const int b = (blockIdx.x << 1) + e;

    const float4* yrow4 = reinterpret_cast<const float4*>(y_pred + (size_t)b * (T_ * V_));

    // Lane l owns states 4l..4l+3 (lane 31 also s=128).
    //  s=4l: blank  s=4l+1: label 2l  s=4l+2: blank  s=4l+3: label 2l+1
    const int* lr = y_true + b * L_;
    const int lab1 = lr[2 * lane];
    const int lab3 = lr[2 * lane + 1];
    const int labp = (lane > 0) ? lr[2 * lane - 1] : 0;
    const float sk1 = (lane > 0 && lab1 != labp) ? 1.0f : 0.0f;
    const float sk3 = (lab3 != lab1) ? 1.0f : 0.0f;

    const int dir = fwd ? 1 : -1;
    const int t0 = fwd ? 0 : 1023;
    const int edge = fwd ? 0 : 31;

    float* const sstW = reinterpret_cast<float*>(&sstage4[wid][0][0][0]);

    float4 rv[8];                       // register row ring for next block
#pragma unroll
    for (int r = 0; r < 8; ++r) rv[r] = yrow4[(t0 + dir * r) * 32 + lane];

    float a0 = 0.f, a1 = 0.f, a2 = 0.f, a3 = 0.f, a4 = 0.f;
    int K = 0;
    float sc = (lane == edge) ? 0.0f : 1.0f;
    float qB, q1, q3, pqB, pq1, pq3;
    float zpart = 0.f;

#define STAGE8(c)                                                             \
    {                                                                         \
        float4* dst = reinterpret_cast<float4*>(sst);                         \
        _Pragma("unroll")                                                     \
        for (int r = 0; r < 8; ++r) {                                         \
            float4 y = rv[r];                                                 \
            dst[r * 32 + lane] = y;                                           \
            szp[wid][((c) * 8 + r) & 15][lane] = (y.x + y.y) + (y.z + y.w);   \
        }                                                                     \
        __syncwarp();                                                         \
    }

#define PREFETCH8(c)                                                          \
    {                                                                         \
        _Pragma("unroll")                                                     \
        for (int r = 0; r < 8; ++r)                                           \
            rv[r] = yrow4[(t0 + dir * (((c) + 1) * 8 + r)) * 32 + lane];      \
    }

#define TRANSPOSE_Z()                                                         \
    {                                                                         \
        int rr = lane & 15;                                                   \
        int j0 = (lane >> 4) << 4;                                            \
        float Zs0 = 0.f, Zs1 = 0.f;                                           \
        _Pragma("unroll")                                                     \
        for (int j = 0; j < 16; j += 2) {                                     \
            Zs0 += szp[wid][rr][j0 + j];                                      \
            Zs1 += szp[wid][rr][j0 + j + 1];                                  \
        }                                                                     \
        float Zs = Zs0 + Zs1;                                                 \
        Zs += __shfl_down_sync(0xffffffffu, Zs, 16);                          \
        if (lane < 16) zpart += lg2(Zs + V_ * EPS_);                          \
        __syncwarp();                                                         \
    }

#define QLDS_TO(r, oB, o1, o3)                                                \
    {                                                                         \
        const float* rw = sst + (r) * 128;                                    \
        oB = rw[127] + EPS_; o1 = rw[lab1] + EPS_; o3 = rw[lab3] + EPS_;      \
    }

#define RENORM(SHFL_EXPR)                                                     \
    {                                                                         \
        float m = fmaxf(fmaxf(fmaxf(a0, a1), fmaxf(a2, a3)), a4);             \
        int ee = (int)(__float_as_uint(m) >> 23);                             \
        int ec = (ee > 0) ? ee : 127;                                         \
        K += ec - 127;                                                        \
        float rsc = __int_as_float((unsigned)(254 - ec) << 23);               \
        a0 *= rsc; a1 *= rsc; a2 *= rsc; a3 *= rsc; a4 *= rsc;                \
        int Kn = SHFL_EXPR;                                                   \
        int d = Kn - K; if (d > 127) d = 127;                                 \
        sc = (d < -126) ? 0.0f : __int_as_float((unsigned)(d + 127) << 23);   \
        if (lane == edge) sc = 0.0f;                                          \
    }

#define FWD_DP()                                                              \
    {                                                                         \
        float hi1 = __shfl_up_sync(0xffffffffu, a3, 1) * sc;                  \
        float n0 = (a0 + hi1) * qB;                                           \
        float n1 = fmaf(sk1, hi1, a0 + a1) * q1;                              \
        float n2 = (a1 + a2) * qB;                                            \
        float n3 = fmaf(sk3, a1, a2 + a3) * q3;                               \
        float n4 = (a3 + a4) * qB;                                            \
        a0 = n0; a1 = n1; a2 = n2; a3 = n3;                                   \
        a4 = (lane == 31) ? n4 : 0.0f;                                        \
    }

// FWD pipelined step: prefetch q(rnext) while DP consumes current q.
#define FWD_STEP_PIPE(rnext)                                                  \
    {                                                                         \
        float tB, t1, t3;                                                     \
        QLDS_TO(rnext, tB, t1, t3);                                           \
        FWD_DP();                                                             \
        qB = tB; q1 = t1; q3 = t3;                                            \
    }

#define BWD_DP()                                                              \
    {                                                                         \
        float c1 = a1 * pq1;                                                  \
        float c3 = a3 * pq3;                                                  \
        float cB2 = a2 * pqB;                                                 \
        float w = c1 * sk1;                                                   \
        float wd = __shfl_down_sync(0xffffffffu, w, 1) * sc;                  \
        float b0d = __shfl_down_sync(0xffffffffu, a0, 1) * sc;                \
        float t1 = (lane == 31) ? a4 : b0d;                                   \
        float t2 = (lane == 31) ? 0.0f : wd;                                  \
        float n0 = fmaf(a0, pqB, c1);                                         \
        float n1 = fmaf(c3, sk3, c1 + cB2);                                   \
        float n2 = cB2 + c3;                                                  \
        float n3 = fmaf(t1, pqB, c3 + t2);                                    \
        float n4 = a4 * pqB;                                                  \
        a0 = n0; a1 = n1; a2 = n2; a3 = n3; a4 = n4;                          \
        pqB = qB; pq1 = q1; pq3 = q3;                                         \
    }

#define SH_UP   __shfl_up_sync(0xffffffffu, K, 1)
#define SH_DN   __shfl_down_sync(0xffffffffu, K, 1)

#define FWD_BLOCK(c, PF)                                                      \
    {                                                                         \
        float* sst = sstW + ((c) & 1) * 1024;                                 \
        STAGE8(c);                                                            \
        if (PF) PREFETCH8(c);                                                 \
        QLDS_TO(0, qB, q1, q3);                                               \
        FWD_STEP_PIPE(1); FWD_STEP_PIPE(2); FWD_STEP_PIPE(3);                 \
        FWD_STEP_PIPE(4); FWD_STEP_PIPE(5); FWD_STEP_PIPE(6);                 \
        FWD_STEP_PIPE(7);                                                     \
        FWD_DP(); RENORM(SH_UP);                                              \
    }

#define BWD_BLOCK(c, PF)                                                      \
    {                                                                         \
        float* sst = sstW + ((c) & 1) * 1024;                                 \
        STAGE8(c);                                                            \
        if (PF) PREFETCH8(c);                                                 \
        QLDS_TO(0, qB, q1, q3); BWD_DP();                                     \
        QLDS_TO(1, qB, q1, q3); BWD_DP();                                     \
        QLDS_TO(2, qB, q1, q3); BWD_DP();                                     \
        QLDS_TO(3, qB, q1, q3); BWD_DP();                                     \
        QLDS_TO(4, qB, q1, q3); BWD_DP();                                     \
        QLDS_TO(5, qB, q1, q3); BWD_DP();                                     \
        QLDS_TO(6, qB, q1, q3); BWD_DP();                                     \
        QLDS_TO(7, qB, q1, q3); BWD_DP();                                     \
        RENORM(SH_DN);                                                        \
    }

    if (fwd) {
        {   // block 0: row 0 is init, rows 1..7 are DP steps 1..7
            float* sst = sstW;
            STAGE8(0);
            PREFETCH8(0);
            QLDS_TO(0, qB, q1, q3);
            if (lane == 0) { a0 = qB; a1 = q1; }            // alpha'_0
            QLDS_TO(1, qB, q1, q3);
            FWD_STEP_PIPE(2); FWD_STEP_PIPE(3); FWD_STEP_PIPE(4);
            FWD_STEP_PIPE(5); FWD_STEP_PIPE(6); FWD_STEP_PIPE(7);
            FWD_DP(); RENORM(SH_UP);
        }
        for (int cp = 0; cp < 31; ++cp) {                   // blocks 1..62
            const int c = 2 * cp + 1;
            FWD_BLOCK(c, true); TRANSPOSE_Z();
            FWD_BLOCK(c + 1, true);
        }
        FWD_BLOCK(63, false); TRANSPOSE_Z();
    } else {
        {   // block 0: row 0 loads q(1023) into pq + init, rows 1..7 DP
            float* sst = sstW;
            STAGE8(0);
            PREFETCH8(0);
            QLDS_TO(0, qB, q1, q3);
            pqB = qB; pq1 = q1; pq3 = q3;
            if (lane == 31) { a3 = 1.0f; a4 = 1.0f; }       // beta_1023
            QLDS_TO(1, qB, q1, q3); BWD_DP();
            QLDS_TO(2, qB, q1, q3); BWD_DP();
            QLDS_TO(3, qB, q1, q3); BWD_DP();
            QLDS_TO(4, qB, q1, q3); BWD_DP();
            QLDS_TO(5, qB, q1, q3); BWD_DP();
            QLDS_TO(6, qB, q1, q3); BWD_DP();
            QLDS_TO(7, qB, q1, q3); BWD_DP();
            RENORM(SH_DN);
        }
        for (int cp = 0; cp < 31; ++cp) {                   // blocks 1..62
            const int c = 2 * cp + 1;
            BWD_BLOCK(c, true); TRANSPOSE_Z();
            BWD_BLOCK(c + 1, true);
        }
        BWD_BLOCK(63, false); TRANSPOSE_Z();
    }

    // per-warp Sum lg2(Z) over its 512 timesteps (lanes >=16 hold 0)
#pragma unroll
    for (int off = 16; off; off >>= 1)
        zpart += __shfl_xor_sync(0xffffffffu, zpart, off);
    if (lane == 0) szHalf[wid] = zpart;

    if (!fwd) {
        float Kf = (float)K;
        sbeta[e][4 * lane + 0] = lg2(a0) + Kf;
        sbeta[e][4 * lane + 1] = lg2(a1) + Kf;
        sbeta[e][4 * lane + 2] = lg2(a2) + Kf;
        sbeta[e][4 * lane + 3] = lg2(a3) + Kf;
        if (lane == 31) sbeta[e][128] = lg2(a4) + Kf;
    }
    __syncthreads();

    if (fwd) {
        // loglik = (LSE_s(log2 alpha'_511 + log2 beta'_511) - szTot) * ln2
        float Kf = (float)K;
        float c0 = lg2(a0) + Kf + sbeta[e][4 * lane + 0];
        float c1 = lg2(a1) + Kf + sbeta[e][4 * lane + 1];
        float c2 = lg2(a2) + Kf + sbeta[e][4 * lane + 2];
        float c3 = lg2(a3) + Kf + sbeta[e][4 * lane + 3];
        float c4 = (lane == 31) ? (lg2(a4) + Kf + sbeta[e][128]) : NEG;
        float m = fmaxf(fmaxf(fmaxf(c0, c1), fmaxf(c2, c3)), c4);
#pragma unroll
        for (int off = 16; off; off >>= 1)
            m = fmaxf(m, __shfl_xor_sync(0xffffffffu, m, off));
        float s = ex2(c0 - m) + ex2(c1 - m) + ex2(c2 - m) + ex2(c3 - m) + ex2(c4 - m);
#pragma unroll
        for (int off = 16; off; off >>= 1)
            s += __shfl_xor_sync(0xffffffffu, s, off);
        if (lane == 0) {
            float szTot = szHalf[wid] + szHalf[wid + 1];
            float loglik = (m + lg2(s) - szTot) * LN2_;
            float loss = -loglik;
            float p = expf(-loss);
            float om = 1.0f - p;
            sfocal[e] = 0.25f * om * om * loss;
        }
    }
    __syncthreads();

    // ---- fused mean: last CTA reduces all 256 focal values in parallel ----
    if (threadIdx.x == 0) {
        const int b0 = blockIdx.x << 1;
        g_focal[b0] = sfocal[0];
        g_focal[b0 + 1] = sfocal[1];
        __threadfence();
        unsigned int old = atomicAdd(&g_count, 1u);
        sIsLast = (old == gridDim.x - 1) ? 1u : 0u;
    }
    __syncthreads();
    if (sIsLast) {
        float v = g_focal[threadIdx.x] + g_focal[threadIdx.x + 128];
#pragma unroll
        for (int off = 16; off; off >>= 1)
            v += __shfl_xor_sync(0xffffffffu, v, off);
        if (lane == 0) sred[wid] = v;
        __syncthreads();
        if (threadIdx.x == 0) {
            out[0] = ((sred[0] + sred[1]) + (sred[2] + sred[3])) * (1.0f / (float)B_);
            g_count = 0;             // reset for next graph replay
        }
    }
}

extern "C" void kernel_launch(void* const* d_in, const int* in_sizes, int n_in,
                              void* d_out, int out_size) {
    const int* y_true;
    const float* y_pred;
    if (in_sizes[0] == B_ * L_) {
        y_true = (const int*)d_in[0];
        y_pred = (const float*)d_in[1];
    } else {
        y_true = (const int*)d_in[1];
        y_pred = (const float*)d_in[0];
    }
    ctc_kernel<<<B_ / 2, 128>>>(y_true, y_pred, (float*)d_out);
}